// round 2
// baseline (speedup 1.0000x reference)
#include <cuda_runtime.h>
#include <cuda_bf16.h>

// Problem constants
#define B_    2
#define N_    4096
#define DIM_  512
#define H_    8
#define DH_   64
#define BN_   (B_*N_)          // 8192 rows
#define INNER (H_*DH_)         // 512

// ---------------- scratch (device globals; no runtime alloc) ----------------
__device__ float g_Q[B_*H_*N_*DH_];      // [b][h][n][d], pre-scaled by 1/64
__device__ float g_K[B_*H_*N_*DH_];
__device__ float g_V[B_*H_*N_*DH_];
__device__ float g_attn[BN_*INNER];      // [b*n][h*DH + d]  (GEMM-ready)

// =====================================================================
// Kernel 1: fused QKV projection
//   C[8192, 1536] = x[8192,512] @ [Wq | Wkv]   (col<512: Q, <1024: K, else V)
//   Q scaled by DH^-1 = 1/64 (reference applies DH^-0.5 twice).
//   Epilogue scatters into [B,H,N,DH] layout.
// =====================================================================
__global__ __launch_bounds__(256) void qkv_gemm_kernel(
    const float* __restrict__ x, const float* __restrict__ Wq,
    const float* __restrict__ Wkv)
{
    __shared__ float As[16][128];   // A transposed: As[k][m]
    __shared__ float Bs[16][128];

    const int bx = blockIdx.x;      // 0..11 (column block of 128)
    const int by = blockIdx.y;      // 0..63 (row block of 128)

    const float* W; int ldw, wcol, which;
    if (bx < 4)      { W = Wq;  ldw = 512;  wcol = bx*128;            which = 0; }
    else if (bx < 8) { W = Wkv; ldw = 1024; wcol = (bx-4)*128;        which = 1; }
    else             { W = Wkv; ldw = 1024; wcol = (bx-8)*128 + 512;  which = 2; }

    const int tid  = threadIdx.x;
    const int trow = (tid >> 4) * 8;   // 0..120
    const int tcol = (tid & 15) * 8;   // 0..120
    const int row0 = by * 128;

    float acc[8][8];
    #pragma unroll
    for (int i = 0; i < 8; i++)
        #pragma unroll
        for (int j = 0; j < 8; j++) acc[i][j] = 0.0f;

    for (int k0 = 0; k0 < 512; k0 += 16) {
        // load A tile (128 rows x 16 k), store transposed
        #pragma unroll
        for (int i = 0; i < 2; i++) {
            int idx = tid*2 + i;                  // 0..511
            int r = idx >> 2, c4 = (idx & 3) * 4;
            float4 v = *(const float4*)&x[(size_t)(row0 + r)*512 + k0 + c4];
            As[c4+0][r] = v.x; As[c4+1][r] = v.y;
            As[c4+2][r] = v.z; As[c4+3][r] = v.w;
        }
        // load B tile (16 k x 128 cols)
        #pragma unroll
        for (int i = 0; i < 2; i++) {
            int idx = tid*2 + i;
            int kk = idx >> 5, c4 = (idx & 31) * 4;
            *(float4*)&Bs[kk][c4] =
                *(const float4*)&W[(size_t)(k0 + kk)*ldw + wcol + c4];
        }
        __syncthreads();

        #pragma unroll
        for (int kk = 0; kk < 16; kk++) {
            float4 alo = *(const float4*)&As[kk][trow];
            float4 ahi = *(const float4*)&As[kk][trow + 4];
            float4 blo = *(const float4*)&Bs[kk][tcol];
            float4 bhi = *(const float4*)&Bs[kk][tcol + 4];
            float a[8] = {alo.x, alo.y, alo.z, alo.w, ahi.x, ahi.y, ahi.z, ahi.w};
            float b[8] = {blo.x, blo.y, blo.z, blo.w, bhi.x, bhi.y, bhi.z, bhi.w};
            #pragma unroll
            for (int i = 0; i < 8; i++)
                #pragma unroll
                for (int j = 0; j < 8; j++)
                    acc[i][j] = fmaf(a[i], b[j], acc[i][j]);
        }
        __syncthreads();
    }

    // epilogue: scatter to [B,H,N,DH]
    const float scale = (which == 0) ? (1.0f/64.0f) : 1.0f;
    float* dst = (which == 0) ? g_Q : (which == 1 ? g_K : g_V);
    const int lcolbase = (which == 0) ? bx*128 : (which == 1 ? (bx-4)*128 : (bx-8)*128);

    #pragma unroll
    for (int i = 0; i < 8; i++) {
        int r = row0 + trow + i;
        int b = r >> 12, n = r & (N_ - 1);
        #pragma unroll
        for (int j = 0; j < 8; j++) {
            int c0 = lcolbase + tcol + j;
            int h = c0 >> 6, d = c0 & 63;
            dst[(((size_t)(b*H_ + h)*N_ + n)*DH_ + d)] = acc[i][j] * scale;
        }
    }
}

// =====================================================================
// Kernel 2: causal flash attention, row-per-thread, scalar FMA.
//   grid (16, 16): y = (b,h); x paired with (31-x) for load balance.
//   128 threads = 128 query rows per tile; K/V tiles of 64 in smem.
// =====================================================================
#define TQ   128
#define TKEY 64
#define NT   (N_ / TQ)   // 32

__global__ __launch_bounds__(128) void flash_kernel()
{
    __shared__ float Ks[TKEY][DH_];   // 16 KB
    __shared__ float Vs[TKEY][DH_];   // 16 KB

    const int bh = blockIdx.y;
    const float* Qb = g_Q + (size_t)bh * N_ * DH_;
    const float* Kb = g_K + (size_t)bh * N_ * DH_;
    const float* Vb = g_V + (size_t)bh * N_ * DH_;
    const int b = bh >> 3, h = bh & 7;

    for (int seq = 0; seq < 2; seq++) {
        const int tile = seq ? (NT - 1 - blockIdx.x) : blockIdx.x;
        const int qrow = tile * TQ + threadIdx.x;

        float q[64], o[64];
        {
            const float4* qp = (const float4*)(Qb + (size_t)qrow * DH_);
            #pragma unroll
            for (int i = 0; i < 16; i++) {
                float4 t = qp[i];
                q[4*i+0] = t.x; q[4*i+1] = t.y; q[4*i+2] = t.z; q[4*i+3] = t.w;
            }
        }
        #pragma unroll
        for (int i = 0; i < 64; i++) o[i] = 0.0f;
        float m = -1e30f, l = 0.0f;

        const int nk = tile * TQ + TQ;           // keys needed (causal)
        for (int k0 = 0; k0 < nk; k0 += TKEY) {
            // cooperative K/V tile load (128 threads x 8 float4 each)
            #pragma unroll
            for (int i = 0; i < 8; i++) {
                int idx = threadIdx.x + i*128;   // 0..1023
                int rr = idx >> 4, c4 = (idx & 15) * 4;
                *(float4*)&Ks[rr][c4] = *(const float4*)&Kb[(size_t)(k0+rr)*DH_ + c4];
                *(float4*)&Vs[rr][c4] = *(const float4*)&Vb[(size_t)(k0+rr)*DH_ + c4];
            }
            __syncthreads();

            #pragma unroll 1
            for (int c0 = 0; c0 < TKEY; c0 += 16) {
                float s[16];
                #pragma unroll 4
                for (int j = 0; j < 16; j++) {
                    const float4* kp = (const float4*)&Ks[c0 + j][0];
                    float a0 = 0.f, a1 = 0.f, a2 = 0.f, a3 = 0.f;
                    #pragma unroll
                    for (int d4 = 0; d4 < 16; d4++) {
                        float4 kv = kp[d4];
                        a0 = fmaf(q[4*d4+0], kv.x, a0);
                        a1 = fmaf(q[4*d4+1], kv.y, a1);
                        a2 = fmaf(q[4*d4+2], kv.z, a2);
                        a3 = fmaf(q[4*d4+3], kv.w, a3);
                    }
                    float sv = (a0 + a1) + (a2 + a3);
                    int kg = k0 + c0 + j;
                    s[j] = (kg <= qrow) ? sv : -1e30f;   // triu(k=1) mask
                }
                // online softmax merge (key 0 always valid -> m finite after chunk 0)
                float mn = m;
                #pragma unroll
                for (int j = 0; j < 16; j++) mn = fmaxf(mn, s[j]);
                float corr = __expf(m - mn);
                m = mn;
                l *= corr;
                #pragma unroll
                for (int i = 0; i < 64; i++) o[i] *= corr;

                #pragma unroll 2
                for (int j = 0; j < 16; j++) {
                    float p = __expf(s[j] - m);          // masked -> exp(-huge)=0
                    l += p;
                    const float4* vp = (const float4*)&Vs[c0 + j][0];
                    #pragma unroll
                    for (int d4 = 0; d4 < 16; d4++) {
                        float4 vv = vp[d4];
                        o[4*d4+0] = fmaf(p, vv.x, o[4*d4+0]);
                        o[4*d4+1] = fmaf(p, vv.y, o[4*d4+1]);
                        o[4*d4+2] = fmaf(p, vv.z, o[4*d4+2]);
                        o[4*d4+3] = fmaf(p, vv.w, o[4*d4+3]);
                    }
                }
            }
            __syncthreads();
        }

        // normalize + store into [b*n][h*DH+d] GEMM-ready layout
        float inv = 1.0f / l;
        float* outp = g_attn + ((size_t)(b*N_ + qrow) * INNER + h*DH_);
        #pragma unroll
        for (int i = 0; i < 16; i++) {
            float4 r;
            r.x = o[4*i+0] * inv; r.y = o[4*i+1] * inv;
            r.z = o[4*i+2] * inv; r.w = o[4*i+3] * inv;
            *(float4*)&outp[4*i] = r;
        }
    }
}

// =====================================================================
// Kernel 3: out = g_attn[8192,512] @ Wo[512,512] + bo
// =====================================================================
__global__ __launch_bounds__(256) void out_gemm_kernel(
    const float* __restrict__ Wo, const float* __restrict__ bo,
    float* __restrict__ out)
{
    __shared__ float As[16][128];
    __shared__ float Bs[16][128];

    const int bx = blockIdx.x;      // 0..3
    const int by = blockIdx.y;      // 0..63
    const int tid  = threadIdx.x;
    const int trow = (tid >> 4) * 8;
    const int tcol = (tid & 15) * 8;
    const int row0 = by * 128;
    const int wcol = bx * 128;

    float acc[8][8];
    #pragma unroll
    for (int i = 0; i < 8; i++)
        #pragma unroll
        for (int j = 0; j < 8; j++) acc[i][j] = 0.0f;

    for (int k0 = 0; k0 < 512; k0 += 16) {
        #pragma unroll
        for (int i = 0; i < 2; i++) {
            int idx = tid*2 + i;
            int r = idx >> 2, c4 = (idx & 3) * 4;
            float4 v = *(const float4*)&g_attn[(size_t)(row0 + r)*512 + k0 + c4];
            As[c4+0][r] = v.x; As[c4+1][r] = v.y;
            As[c4+2][r] = v.z; As[c4+3][r] = v.w;
        }
        #pragma unroll
        for (int i = 0; i < 2; i++) {
            int idx = tid*2 + i;
            int kk = idx >> 5, c4 = (idx & 31) * 4;
            *(float4*)&Bs[kk][c4] =
                *(const float4*)&Wo[(size_t)(k0 + kk)*512 + wcol + c4];
        }
        __syncthreads();

        #pragma unroll
        for (int kk = 0; kk < 16; kk++) {
            float4 alo = *(const float4*)&As[kk][trow];
            float4 ahi = *(const float4*)&As[kk][trow + 4];
            float4 blo = *(const float4*)&Bs[kk][tcol];
            float4 bhi = *(const float4*)&Bs[kk][tcol + 4];
            float a[8] = {alo.x, alo.y, alo.z, alo.w, ahi.x, ahi.y, ahi.z, ahi.w};
            float b[8] = {blo.x, blo.y, blo.z, blo.w, bhi.x, bhi.y, bhi.z, bhi.w};
            #pragma unroll
            for (int i = 0; i < 8; i++)
                #pragma unroll
                for (int j = 0; j < 8; j++)
                    acc[i][j] = fmaf(a[i], b[j], acc[i][j]);
        }
        __syncthreads();
    }

    #pragma unroll
    for (int i = 0; i < 8; i++) {
        int r = row0 + trow + i;
        #pragma unroll
        for (int j = 0; j < 8; j++) {
            int c0 = wcol + tcol + j;
            out[(size_t)r*512 + c0] = acc[i][j] + bo[c0];
        }
    }
}

// =====================================================================
extern "C" void kernel_launch(void* const* d_in, const int* in_sizes, int n_in,
                              void* d_out, int out_size)
{
    const float* x   = (const float*)d_in[0];
    const float* Wq  = (const float*)d_in[1];
    const float* Wkv = (const float*)d_in[2];
    const float* Wo  = (const float*)d_in[3];
    const float* bo  = (const float*)d_in[4];
    float* out = (float*)d_out;

    qkv_gemm_kernel<<<dim3(12, 64), 256>>>(x, Wq, Wkv);
    flash_kernel<<<dim3(NT/2, B_*H_), 128>>>();
    out_gemm_kernel<<<dim3(4, 64), 256>>>(Wo, bo, out);
}

// round 3
// speedup vs baseline: 3.5112x; 3.5112x over previous
#include <cuda_runtime.h>

// Problem constants
#define B_    2
#define N_    4096
#define DIM_  512
#define H_    8
#define DH_   64
#define BN_   (B_*N_)          // 8192 rows
#define INNER (H_*DH_)         // 512

// ---------------- scratch (device globals; no runtime alloc) ----------------
__device__ float g_Q[B_*H_*N_*DH_];      // [b][h][n][d], pre-scaled by 1/64
__device__ float g_K[B_*H_*N_*DH_];
__device__ float g_V[B_*H_*N_*DH_];
__device__ float g_attn[BN_*INNER];      // [b*n][h*DH + d]  (GEMM-ready)

// ---------------- tf32 mma helpers ----------------
__device__ __forceinline__ unsigned f2tf(float f) {
    unsigned u; asm("cvt.rna.tf32.f32 %0, %1;" : "=r"(u) : "f"(f)); return u;
}
// D += A(16x8,row) * B(8x8,col) ; tf32 inputs, f32 accum
__device__ __forceinline__ void mma8(float* c, const unsigned* a, unsigned b0, unsigned b1) {
    asm("mma.sync.aligned.m16n8k8.row.col.f32.tf32.tf32.f32 "
        "{%0,%1,%2,%3}, {%4,%5,%6,%7}, {%8,%9}, {%0,%1,%2,%3};"
        : "+f"(c[0]), "+f"(c[1]), "+f"(c[2]), "+f"(c[3])
        : "r"(a[0]), "r"(a[1]), "r"(a[2]), "r"(a[3]), "r"(b0), "r"(b1));
}

// =====================================================================
// Shared tf32 GEMM core: C[128x128] = A[128x512] * W[512, ldw] (cols wcol..)
// 256 threads, 8 warps (2x4), warp tile 64x32.
// As layout [m][k] stride 20 ; Bs layout [k][n] stride 136.
// =====================================================================
#define AS_STRIDE 20
#define BS_STRIDE 136

__device__ __forceinline__ void gemm_tf32_core(
    const float* __restrict__ A, const float* __restrict__ Wsrc,
    int ldw, int wcol, int row0,
    float (&acc)[4][4][4], unsigned* As, unsigned* Bs)
{
    const int tid  = threadIdx.x;
    const int lane = tid & 31, w = tid >> 5;
    const int gid  = lane >> 2, tig = lane & 3;
    const int m0w  = (w >> 2) * 64;
    const int n0w  = (w & 3) * 32;

    #pragma unroll
    for (int mt = 0; mt < 4; mt++)
        #pragma unroll
        for (int nt = 0; nt < 4; nt++)
            #pragma unroll
            for (int r = 0; r < 4; r++) acc[mt][nt][r] = 0.0f;

    for (int k0 = 0; k0 < 512; k0 += 16) {
        __syncthreads();
        // stage A: 128 rows x 16 k  (natural [m][k])
        #pragma unroll
        for (int i = 0; i < 2; i++) {
            int idx = tid + i*256;                 // 0..511
            int r = idx >> 2, c4 = (idx & 3) * 4;
            float4 v = *(const float4*)&A[(size_t)(row0 + r)*512 + k0 + c4];
            uint4 u = make_uint4(f2tf(v.x), f2tf(v.y), f2tf(v.z), f2tf(v.w));
            *(uint4*)&As[r*AS_STRIDE + c4] = u;
        }
        // stage B: 16 k x 128 n
        #pragma unroll
        for (int i = 0; i < 2; i++) {
            int idx = tid + i*256;
            int kk = idx >> 5, c4 = (idx & 31) * 4;
            float4 v = *(const float4*)&Wsrc[(size_t)(k0 + kk)*ldw + wcol + c4];
            uint4 u = make_uint4(f2tf(v.x), f2tf(v.y), f2tf(v.z), f2tf(v.w));
            *(uint4*)&Bs[kk*BS_STRIDE + c4] = u;
        }
        __syncthreads();

        #pragma unroll
        for (int kc = 0; kc < 2; kc++) {
            const int kk = kc * 8;
            unsigned am[4][4];
            #pragma unroll
            for (int mt = 0; mt < 4; mt++) {
                int mr = m0w + mt*16;
                am[mt][0] = As[(mr+gid  )*AS_STRIDE + kk + tig    ];
                am[mt][1] = As[(mr+gid+8)*AS_STRIDE + kk + tig    ];
                am[mt][2] = As[(mr+gid  )*AS_STRIDE + kk + tig + 4];
                am[mt][3] = As[(mr+gid+8)*AS_STRIDE + kk + tig + 4];
            }
            unsigned bn[4][2];
            #pragma unroll
            for (int nt = 0; nt < 4; nt++) {
                bn[nt][0] = Bs[(kk+tig  )*BS_STRIDE + n0w + nt*8 + gid];
                bn[nt][1] = Bs[(kk+tig+4)*BS_STRIDE + n0w + nt*8 + gid];
            }
            #pragma unroll
            for (int mt = 0; mt < 4; mt++)
                #pragma unroll
                for (int nt = 0; nt < 4; nt++)
                    mma8(acc[mt][nt], am[mt], bn[nt][0], bn[nt][1]);
        }
    }
}

// =====================================================================
// Kernel 1: QKV projection -> scatter to [B,H,N,DH] (Q scaled by 1/64)
// =====================================================================
__global__ __launch_bounds__(256, 2) void qkv_mma_kernel(
    const float* __restrict__ x, const float* __restrict__ Wq,
    const float* __restrict__ Wkv)
{
    __shared__ unsigned As[128*AS_STRIDE];
    __shared__ unsigned Bs[16*BS_STRIDE];

    const int bx = blockIdx.x;   // 0..11
    const int by = blockIdx.y;   // 0..63
    const int row0 = by * 128;

    const float* W; int ldw, wcol, which;
    if (bx < 4)      { W = Wq;  ldw = 512;  wcol = bx*128;            which = 0; }
    else if (bx < 8) { W = Wkv; ldw = 1024; wcol = (bx-4)*128;        which = 1; }
    else             { W = Wkv; ldw = 1024; wcol = (bx-8)*128 + 512;  which = 2; }

    float acc[4][4][4];
    gemm_tf32_core(x, W, ldw, wcol, row0, acc, As, Bs);

    const float scale = (which == 0) ? (1.0f/64.0f) : 1.0f;
    float* dst = (which == 0) ? g_Q : (which == 1 ? g_K : g_V);
    const int lcolbase = (which == 0) ? bx*128 : (which == 1 ? (bx-4)*128 : (bx-8)*128);

    const int lane = threadIdx.x & 31, w = threadIdx.x >> 5;
    const int gid = lane >> 2, tig = lane & 3;
    const int m0w = (w >> 2) * 64, n0w = (w & 3) * 32;

    #pragma unroll
    for (int mt = 0; mt < 4; mt++) {
        int r0 = row0 + m0w + mt*16 + gid;
        int r1 = r0 + 8;
        int b0i = r0 >> 12, n0i = r0 & (N_-1);
        int b1i = r1 >> 12, n1i = r1 & (N_-1);
        #pragma unroll
        for (int nt = 0; nt < 4; nt++) {
            int c = lcolbase + n0w + nt*8 + 2*tig;
            int h = c >> 6, d = c & 63;
            float2 v0 = make_float2(acc[mt][nt][0]*scale, acc[mt][nt][1]*scale);
            float2 v1 = make_float2(acc[mt][nt][2]*scale, acc[mt][nt][3]*scale);
            *(float2*)&dst[(((size_t)(b0i*H_ + h)*N_ + n0i)*DH_ + d)] = v0;
            *(float2*)&dst[(((size_t)(b1i*H_ + h)*N_ + n1i)*DH_ + d)] = v1;
        }
    }
}

// =====================================================================
// Kernel 2: causal flash attention with tf32 mma.
//   Block: 128 threads (4 warps), 64 q-rows (16/warp), K/V tiles of 64.
//   grid (64, 16): tile = 63 - bx (big tiles first), y = (b,h).
// =====================================================================
#define KS_STRIDE 68
#define VS_STRIDE 72

__global__ __launch_bounds__(128, 3) void flash_mma_kernel()
{
    __shared__ unsigned Ks[64*KS_STRIDE];   // also used to stage Q
    __shared__ unsigned Vs[64*VS_STRIDE];

    const int bh = blockIdx.y, b = bh >> 3, h = bh & 7;
    const int tile = 63 - blockIdx.x;
    const int tid = threadIdx.x, lane = tid & 31, w = tid >> 5;
    const int gid = lane >> 2, tig = lane & 3;

    const float* Qb = g_Q + (size_t)bh * N_ * DH_;
    const float* Kb = g_K + (size_t)bh * N_ * DH_;
    const float* Vb = g_V + (size_t)bh * N_ * DH_;
    const int qrow0 = tile * 64;

    // ---- stage Q tile into Ks buffer (tf32), load A fragments ----
    #pragma unroll
    for (int i = 0; i < 8; i++) {
        int idx = tid + i*128;
        int rr = idx >> 4, c4 = (idx & 15) * 4;
        float4 v = *(const float4*)&Qb[(size_t)(qrow0+rr)*DH_ + c4];
        *(uint4*)&Ks[rr*KS_STRIDE + c4] =
            make_uint4(f2tf(v.x), f2tf(v.y), f2tf(v.z), f2tf(v.w));
    }
    __syncthreads();
    unsigned aq[8][4];
    {
        const unsigned* Qw = Ks + (16*w)*KS_STRIDE;
        #pragma unroll
        for (int kc = 0; kc < 8; kc++) {
            aq[kc][0] = Qw[(gid  )*KS_STRIDE + kc*8 + tig    ];
            aq[kc][1] = Qw[(gid+8)*KS_STRIDE + kc*8 + tig    ];
            aq[kc][2] = Qw[(gid  )*KS_STRIDE + kc*8 + tig + 4];
            aq[kc][3] = Qw[(gid+8)*KS_STRIDE + kc*8 + tig + 4];
        }
    }

    float oc[8][4];
    #pragma unroll
    for (int jd = 0; jd < 8; jd++)
        #pragma unroll
        for (int r = 0; r < 4; r++) oc[jd][r] = 0.0f;
    float m_r = -1e30f, m_r8 = -1e30f, l_r = 0.0f, l_r8 = 0.0f;
    const int row_r = qrow0 + 16*w + gid, row_r8 = row_r + 8;

    const int nkt = tile + 1;
    for (int kt = 0; kt < nkt; kt++) {
        const int k0 = kt * 64;
        __syncthreads();
        // stage K, V tiles (tf32)
        #pragma unroll
        for (int i = 0; i < 8; i++) {
            int idx = tid + i*128;
            int rr = idx >> 4, c4 = (idx & 15) * 4;
            float4 kv = *(const float4*)&Kb[(size_t)(k0+rr)*DH_ + c4];
            float4 vv = *(const float4*)&Vb[(size_t)(k0+rr)*DH_ + c4];
            *(uint4*)&Ks[rr*KS_STRIDE + c4] =
                make_uint4(f2tf(kv.x), f2tf(kv.y), f2tf(kv.z), f2tf(kv.w));
            *(uint4*)&Vs[rr*VS_STRIDE + c4] =
                make_uint4(f2tf(vv.x), f2tf(vv.y), f2tf(vv.z), f2tf(vv.w));
        }
        __syncthreads();

        // ---- S = Q K^T  (16 x 64 per warp) ----
        float s[8][4];
        #pragma unroll
        for (int j = 0; j < 8; j++) {
            float sc[4] = {0.f, 0.f, 0.f, 0.f};
            const unsigned* kr = Ks + (j*8+gid)*KS_STRIDE;
            #pragma unroll
            for (int kc = 0; kc < 8; kc++)
                mma8(sc, aq[kc], kr[kc*8 + tig], kr[kc*8 + tig + 4]);
            s[j][0] = sc[0]; s[j][1] = sc[1]; s[j][2] = sc[2]; s[j][3] = sc[3];
        }
        // causal mask (only diagonal tile can violate)
        if (kt == nkt - 1) {
            #pragma unroll
            for (int j = 0; j < 8; j++) {
                int c0 = k0 + j*8 + 2*tig;
                if (c0     > row_r ) s[j][0] = -1e30f;
                if (c0 + 1 > row_r ) s[j][1] = -1e30f;
                if (c0     > row_r8) s[j][2] = -1e30f;
                if (c0 + 1 > row_r8) s[j][3] = -1e30f;
            }
        }
        // ---- online softmax (rows live in 4-lane quads) ----
        float mx_r = -1e30f, mx_r8 = -1e30f;
        #pragma unroll
        for (int j = 0; j < 8; j++) {
            mx_r  = fmaxf(mx_r,  fmaxf(s[j][0], s[j][1]));
            mx_r8 = fmaxf(mx_r8, fmaxf(s[j][2], s[j][3]));
        }
        mx_r  = fmaxf(mx_r,  __shfl_xor_sync(0xffffffffu, mx_r,  1));
        mx_r  = fmaxf(mx_r,  __shfl_xor_sync(0xffffffffu, mx_r,  2));
        mx_r8 = fmaxf(mx_r8, __shfl_xor_sync(0xffffffffu, mx_r8, 1));
        mx_r8 = fmaxf(mx_r8, __shfl_xor_sync(0xffffffffu, mx_r8, 2));
        float mn_r  = fmaxf(m_r,  mx_r);
        float mn_r8 = fmaxf(m_r8, mx_r8);
        float corr_r  = __expf(m_r  - mn_r);
        float corr_r8 = __expf(m_r8 - mn_r8);
        m_r = mn_r; m_r8 = mn_r8;

        float ps_r = 0.0f, ps_r8 = 0.0f;
        unsigned pu[8][4];
        #pragma unroll
        for (int j = 0; j < 8; j++) {
            float p0 = __expf(s[j][0] - m_r);
            float p1 = __expf(s[j][1] - m_r);
            float p2 = __expf(s[j][2] - m_r8);
            float p3 = __expf(s[j][3] - m_r8);
            ps_r  += p0 + p1;
            ps_r8 += p2 + p3;
            pu[j][0] = f2tf(p0); pu[j][1] = f2tf(p1);
            pu[j][2] = f2tf(p2); pu[j][3] = f2tf(p3);
        }
        ps_r  += __shfl_xor_sync(0xffffffffu, ps_r,  1);
        ps_r  += __shfl_xor_sync(0xffffffffu, ps_r,  2);
        ps_r8 += __shfl_xor_sync(0xffffffffu, ps_r8, 1);
        ps_r8 += __shfl_xor_sync(0xffffffffu, ps_r8, 2);
        l_r  = l_r  * corr_r  + ps_r;
        l_r8 = l_r8 * corr_r8 + ps_r8;
        #pragma unroll
        for (int jd = 0; jd < 8; jd++) {
            oc[jd][0] *= corr_r;  oc[jd][1] *= corr_r;
            oc[jd][2] *= corr_r8; oc[jd][3] *= corr_r8;
        }

        // ---- O += P V : convert P C-layout -> A-layout via quad shuffles ----
        const int srcA = (gid << 2) + (tig >> 1);
        const int srcB = srcA + 2;
        const bool odd = (tig & 1);
        #pragma unroll
        for (int j = 0; j < 8; j++) {       // k-chunk = key n-tile j
            unsigned q0A = __shfl_sync(0xffffffffu, pu[j][0], srcA);
            unsigned q1A = __shfl_sync(0xffffffffu, pu[j][1], srcA);
            unsigned q2A = __shfl_sync(0xffffffffu, pu[j][2], srcA);
            unsigned q3A = __shfl_sync(0xffffffffu, pu[j][3], srcA);
            unsigned q0B = __shfl_sync(0xffffffffu, pu[j][0], srcB);
            unsigned q1B = __shfl_sync(0xffffffffu, pu[j][1], srcB);
            unsigned q2B = __shfl_sync(0xffffffffu, pu[j][2], srcB);
            unsigned q3B = __shfl_sync(0xffffffffu, pu[j][3], srcB);
            unsigned ap[4];
            ap[0] = odd ? q1A : q0A;
            ap[1] = odd ? q3A : q2A;
            ap[2] = odd ? q1B : q0B;
            ap[3] = odd ? q3B : q2B;
            #pragma unroll
            for (int jd = 0; jd < 8; jd++)
                mma8(oc[jd], ap,
                     Vs[(j*8+tig  )*VS_STRIDE + jd*8 + gid],
                     Vs[(j*8+tig+4)*VS_STRIDE + jd*8 + gid]);
        }
    }

    // ---- epilogue: normalize, store to [b*n][h*64+d] ----
    float inv_r = 1.0f / l_r, inv_r8 = 1.0f / l_r8;
    float* o0 = g_attn + ((size_t)(b*N_ + row_r )*INNER + h*DH_);
    float* o1 = g_attn + ((size_t)(b*N_ + row_r8)*INNER + h*DH_);
    #pragma unroll
    for (int jd = 0; jd < 8; jd++) {
        int c = jd*8 + 2*tig;
        *(float2*)&o0[c] = make_float2(oc[jd][0]*inv_r,  oc[jd][1]*inv_r );
        *(float2*)&o1[c] = make_float2(oc[jd][2]*inv_r8, oc[jd][3]*inv_r8);
    }
}

// =====================================================================
// Kernel 3: out = g_attn[8192,512] @ Wo[512,512] + bo
// =====================================================================
__global__ __launch_bounds__(256, 2) void out_mma_kernel(
    const float* __restrict__ Wo, const float* __restrict__ bo,
    float* __restrict__ out)
{
    __shared__ unsigned As[128*AS_STRIDE];
    __shared__ unsigned Bs[16*BS_STRIDE];

    const int bx = blockIdx.x;   // 0..3
    const int by = blockIdx.y;   // 0..63
    const int row0 = by * 128;
    const int wcol = bx * 128;

    float acc[4][4][4];
    gemm_tf32_core(g_attn, Wo, 512, wcol, row0, acc, As, Bs);

    const int lane = threadIdx.x & 31, w = threadIdx.x >> 5;
    const int gid = lane >> 2, tig = lane & 3;
    const int m0w = (w >> 2) * 64, n0w = (w & 3) * 32;

    #pragma unroll
    for (int mt = 0; mt < 4; mt++) {
        int r0 = row0 + m0w + mt*16 + gid;
        int r1 = r0 + 8;
        #pragma unroll
        for (int nt = 0; nt < 4; nt++) {
            int c = wcol + n0w + nt*8 + 2*tig;
            float2 bias = *(const float2*)&bo[c];
            float2 v0 = make_float2(acc[mt][nt][0] + bias.x, acc[mt][nt][1] + bias.y);
            float2 v1 = make_float2(acc[mt][nt][2] + bias.x, acc[mt][nt][3] + bias.y);
            *(float2*)&out[(size_t)r0*512 + c] = v0;
            *(float2*)&out[(size_t)r1*512 + c] = v1;
        }
    }
}

// =====================================================================
extern "C" void kernel_launch(void* const* d_in, const int* in_sizes, int n_in,
                              void* d_out, int out_size)
{
    const float* x   = (const float*)d_in[0];
    const float* Wq  = (const float*)d_in[1];
    const float* Wkv = (const float*)d_in[2];
    const float* Wo  = (const float*)d_in[3];
    const float* bo  = (const float*)d_in[4];
    float* out = (float*)d_out;

    qkv_mma_kernel<<<dim3(12, 64), 256>>>(x, Wq, Wkv);
    flash_mma_kernel<<<dim3(64, B_*H_), 128>>>();
    out_mma_kernel<<<dim3(4, 64), 256>>>(Wo, bo, out);
}

// round 4
// speedup vs baseline: 3.5356x; 1.0070x over previous
#include <cuda_runtime.h>

// Problem constants
#define B_    2
#define N_    4096
#define DIM_  512
#define H_    8
#define DH_   64
#define BN_   (B_*N_)          // 8192 rows
#define INNER (H_*DH_)         // 512

// ---------------- scratch (device globals; no runtime alloc) ----------------
// All tf32 payloads stored as raw 32-bit patterns (unsigned).
__device__ unsigned g_x  [BN_*DIM_];        // x converted to tf32
__device__ unsigned g_Wq [DIM_*INNER];
__device__ unsigned g_Wkv[DIM_*2*INNER];
__device__ unsigned g_Wo [INNER*DIM_];
__device__ unsigned g_Q  [B_*H_*N_*DH_];    // [b][h][n][d], pre-scaled by 1/64, tf32
__device__ unsigned g_K  [B_*H_*N_*DH_];
__device__ unsigned g_V  [B_*H_*N_*DH_];
__device__ unsigned g_attn[BN_*INNER];      // [b*n][h*DH+d], tf32

// ---------------- helpers ----------------
__device__ __forceinline__ unsigned f2tf(float f) {
    unsigned u; asm("cvt.rna.tf32.f32 %0, %1;" : "=r"(u) : "f"(f)); return u;
}
__device__ __forceinline__ void mma8(float* c, const unsigned* a, unsigned b0, unsigned b1) {
    asm("mma.sync.aligned.m16n8k8.row.col.f32.tf32.tf32.f32 "
        "{%0,%1,%2,%3}, {%4,%5,%6,%7}, {%8,%9}, {%0,%1,%2,%3};"
        : "+f"(c[0]), "+f"(c[1]), "+f"(c[2]), "+f"(c[3])
        : "r"(a[0]), "r"(a[1]), "r"(a[2]), "r"(a[3]), "r"(b0), "r"(b1));
}
__device__ __forceinline__ void cpa16(unsigned* smem_dst, const unsigned* gsrc) {
    unsigned s = (unsigned)__cvta_generic_to_shared(smem_dst);
    asm volatile("cp.async.cg.shared.global [%0], [%1], 16;" :: "r"(s), "l"(gsrc));
}
__device__ __forceinline__ void cpa_commit() { asm volatile("cp.async.commit_group;"); }
template<int NN> __device__ __forceinline__ void cpa_wait() {
    asm volatile("cp.async.wait_group %0;" :: "n"(NN));
}

// =====================================================================
// Kernel 0: elementwise fp32 -> tf32 convert (vectorized)
// =====================================================================
__global__ void cvt_tf32_kernel(const float4* __restrict__ src,
                                uint4* __restrict__ dst, int n4)
{
    int i = blockIdx.x * blockDim.x + threadIdx.x;
    if (i < n4) {
        float4 v = src[i];
        dst[i] = make_uint4(f2tf(v.x), f2tf(v.y), f2tf(v.z), f2tf(v.w));
    }
}

// =====================================================================
// Shared tf32 GEMM core, cp.async double-buffered.
// C[128x128] = A[128x512](tf32) * W[512,ldw](tf32), 256 thr / 8 warps, warp 64x32.
// =====================================================================
#define AS_STRIDE 20
#define BS_STRIDE 136
#define AS_SZ (128*AS_STRIDE)   // 2560
#define BS_SZ (16*BS_STRIDE)    // 2176

__device__ __forceinline__ void gemm_stage(
    const unsigned* __restrict__ A, const unsigned* __restrict__ W,
    int ldw, int wcol, int row0, int k0, unsigned* As, unsigned* Bs, int tid)
{
    #pragma unroll
    for (int i = 0; i < 2; i++) {
        int idx = tid + i*256;                 // 0..511
        int r = idx >> 2, c4 = (idx & 3) * 4;
        cpa16(&As[r*AS_STRIDE + c4], &A[(size_t)(row0 + r)*512 + k0 + c4]);
    }
    #pragma unroll
    for (int i = 0; i < 2; i++) {
        int idx = tid + i*256;
        int kk = idx >> 5, c4 = (idx & 31) * 4;
        cpa16(&Bs[kk*BS_STRIDE + c4], &W[(size_t)(k0 + kk)*ldw + wcol + c4]);
    }
}

__device__ __forceinline__ void gemm_tf32_db(
    const unsigned* __restrict__ A, const unsigned* __restrict__ W,
    int ldw, int wcol, int row0,
    float (&acc)[4][4][4], unsigned* AsBuf, unsigned* BsBuf)
{
    const int tid  = threadIdx.x;
    const int lane = tid & 31, w = tid >> 5;
    const int gid  = lane >> 2, tig = lane & 3;
    const int m0w  = (w >> 2) * 64;
    const int n0w  = (w & 3) * 32;

    #pragma unroll
    for (int mt = 0; mt < 4; mt++)
        #pragma unroll
        for (int nt = 0; nt < 4; nt++)
            #pragma unroll
            for (int r = 0; r < 4; r++) acc[mt][nt][r] = 0.0f;

    gemm_stage(A, W, ldw, wcol, row0, 0, AsBuf, BsBuf, tid);
    cpa_commit();

    for (int it = 0; it < 32; it++) {
        const int buf = it & 1;
        if (it + 1 < 32) {
            gemm_stage(A, W, ldw, wcol, row0, (it+1)*16,
                       AsBuf + (buf^1)*AS_SZ, BsBuf + (buf^1)*BS_SZ, tid);
            cpa_commit();
            cpa_wait<1>();
        } else {
            cpa_wait<0>();
        }
        __syncthreads();

        const unsigned* As = AsBuf + buf*AS_SZ;
        const unsigned* Bs = BsBuf + buf*BS_SZ;
        #pragma unroll
        for (int kc = 0; kc < 2; kc++) {
            const int kk = kc * 8;
            unsigned am[4][4];
            #pragma unroll
            for (int mt = 0; mt < 4; mt++) {
                int mr = m0w + mt*16;
                am[mt][0] = As[(mr+gid  )*AS_STRIDE + kk + tig    ];
                am[mt][1] = As[(mr+gid+8)*AS_STRIDE + kk + tig    ];
                am[mt][2] = As[(mr+gid  )*AS_STRIDE + kk + tig + 4];
                am[mt][3] = As[(mr+gid+8)*AS_STRIDE + kk + tig + 4];
            }
            unsigned bn[4][2];
            #pragma unroll
            for (int nt = 0; nt < 4; nt++) {
                bn[nt][0] = Bs[(kk+tig  )*BS_STRIDE + n0w + nt*8 + gid];
                bn[nt][1] = Bs[(kk+tig+4)*BS_STRIDE + n0w + nt*8 + gid];
            }
            #pragma unroll
            for (int mt = 0; mt < 4; mt++)
                #pragma unroll
                for (int nt = 0; nt < 4; nt++)
                    mma8(acc[mt][nt], am[mt], bn[nt][0], bn[nt][1]);
        }
        __syncthreads();
    }
}

// =====================================================================
// Kernel 1: QKV projection -> scatter tf32 to [B,H,N,DH] (Q scaled 1/64)
// =====================================================================
__global__ __launch_bounds__(256, 2) void qkv_mma_kernel()
{
    __shared__ unsigned As[2*AS_SZ];
    __shared__ unsigned Bs[2*BS_SZ];

    const int bx = blockIdx.x;   // 0..11
    const int by = blockIdx.y;   // 0..63
    const int row0 = by * 128;

    const unsigned* W; int ldw, wcol, which;
    if (bx < 4)      { W = g_Wq;  ldw = 512;  wcol = bx*128;            which = 0; }
    else if (bx < 8) { W = g_Wkv; ldw = 1024; wcol = (bx-4)*128;        which = 1; }
    else             { W = g_Wkv; ldw = 1024; wcol = (bx-8)*128 + 512;  which = 2; }

    float acc[4][4][4];
    gemm_tf32_db(g_x, W, ldw, wcol, row0, acc, As, Bs);

    const float scale = (which == 0) ? (1.0f/64.0f) : 1.0f;
    unsigned* dst = (which == 0) ? g_Q : (which == 1 ? g_K : g_V);
    const int lcolbase = (which == 0) ? bx*128 : (which == 1 ? (bx-4)*128 : (bx-8)*128);

    const int lane = threadIdx.x & 31, w = threadIdx.x >> 5;
    const int gid = lane >> 2, tig = lane & 3;
    const int m0w = (w >> 2) * 64, n0w = (w & 3) * 32;

    #pragma unroll
    for (int mt = 0; mt < 4; mt++) {
        int r0 = row0 + m0w + mt*16 + gid;
        int r1 = r0 + 8;
        int b0i = r0 >> 12, n0i = r0 & (N_-1);
        int b1i = r1 >> 12, n1i = r1 & (N_-1);
        #pragma unroll
        for (int nt = 0; nt < 4; nt++) {
            int c = lcolbase + n0w + nt*8 + 2*tig;
            int h = c >> 6, d = c & 63;
            uint2 v0 = make_uint2(f2tf(acc[mt][nt][0]*scale), f2tf(acc[mt][nt][1]*scale));
            uint2 v1 = make_uint2(f2tf(acc[mt][nt][2]*scale), f2tf(acc[mt][nt][3]*scale));
            *(uint2*)&dst[(((size_t)(b0i*H_ + h)*N_ + n0i)*DH_ + d)] = v0;
            *(uint2*)&dst[(((size_t)(b1i*H_ + h)*N_ + n1i)*DH_ + d)] = v1;
        }
    }
}

// =====================================================================
// Kernel 2: causal flash attention, tf32 mma, cp.async double-buffered K/V.
//   Block: 256 threads (8 warps), 128 q-rows (16/warp), K/V tiles of 32.
//   grid (32, 16): tile = 31 - bx (big first), y = (b,h).
// =====================================================================
#define KT 32
#define KS_STRIDE 68
#define VS_STRIDE 72
#define KS_SZ (KT*KS_STRIDE)   // 2176
#define VS_SZ (KT*VS_STRIDE)   // 2304

__global__ __launch_bounds__(256, 2) void flash_mma_kernel()
{
    __shared__ unsigned smemU[2*KS_SZ + 2*VS_SZ];   // 35.8 KB
    unsigned* Ks = smemU;
    unsigned* Vs = smemU + 2*KS_SZ;

    const int bh = blockIdx.y, b = bh >> 3, h = bh & 7;
    const int tile = 31 - (int)blockIdx.x;
    const int tid = threadIdx.x, lane = tid & 31, w = tid >> 5;
    const int gid = lane >> 2, tig = lane & 3;

    const unsigned* Qb = g_Q + (size_t)bh * N_ * DH_;
    const unsigned* Kb = g_K + (size_t)bh * N_ * DH_;
    const unsigned* Vb = g_V + (size_t)bh * N_ * DH_;
    const int qrow0 = tile * 128;

    // ---- stage Q tile (128 x 64) into smem once; load A fragments ----
    #pragma unroll
    for (int i = 0; i < 8; i++) {
        int idx = tid + i*256;                // 0..2047
        int rr = idx >> 4, c4 = (idx & 15) * 4;
        cpa16(&smemU[rr*KS_STRIDE + c4], &Qb[(size_t)(qrow0+rr)*DH_ + c4]);
    }
    cpa_commit(); cpa_wait<0>();
    __syncthreads();
    unsigned aq[8][4];
    {
        const unsigned* Qw = smemU + (16*w)*KS_STRIDE;
        #pragma unroll
        for (int kc = 0; kc < 8; kc++) {
            aq[kc][0] = Qw[(gid  )*KS_STRIDE + kc*8 + tig    ];
            aq[kc][1] = Qw[(gid+8)*KS_STRIDE + kc*8 + tig    ];
            aq[kc][2] = Qw[(gid  )*KS_STRIDE + kc*8 + tig + 4];
            aq[kc][3] = Qw[(gid+8)*KS_STRIDE + kc*8 + tig + 4];
        }
    }
    __syncthreads();   // Q reads done before K/V staging overwrites

    float oc[8][4];
    #pragma unroll
    for (int jd = 0; jd < 8; jd++)
        #pragma unroll
        for (int r = 0; r < 4; r++) oc[jd][r] = 0.0f;
    float m_r = -1e30f, m_r8 = -1e30f, l_r = 0.0f, l_r8 = 0.0f;
    const int wrow_min = qrow0 + 16*w;
    const int row_r = wrow_min + gid, row_r8 = row_r + 8;

    const int nkt = (qrow0 + 128) / KT;       // 4*(tile+1)

    // stage first K/V tile
    #pragma unroll
    for (int i = 0; i < 2; i++) {
        int idx = tid + i*256;                // 0..511
        int rr = idx >> 4, c4 = (idx & 15) * 4;
        cpa16(&Ks[rr*KS_STRIDE + c4], &Kb[(size_t)rr*DH_ + c4]);
        cpa16(&Vs[rr*VS_STRIDE + c4], &Vb[(size_t)rr*DH_ + c4]);
    }
    cpa_commit();

    for (int kt = 0; kt < nkt; kt++) {
        const int k0 = kt * KT;
        const int buf = kt & 1;
        if (kt + 1 < nkt) {
            const int kn = k0 + KT;
            unsigned* Kd = Ks + (buf^1)*KS_SZ;
            unsigned* Vd = Vs + (buf^1)*VS_SZ;
            #pragma unroll
            for (int i = 0; i < 2; i++) {
                int idx = tid + i*256;
                int rr = idx >> 4, c4 = (idx & 15) * 4;
                cpa16(&Kd[rr*KS_STRIDE + c4], &Kb[(size_t)(kn+rr)*DH_ + c4]);
                cpa16(&Vd[rr*VS_STRIDE + c4], &Vb[(size_t)(kn+rr)*DH_ + c4]);
            }
            cpa_commit();
            cpa_wait<1>();
        } else {
            cpa_wait<0>();
        }
        __syncthreads();

        const bool active = (k0 <= wrow_min + 15);   // warp-uniform
        if (active) {
            const unsigned* Kbuf = Ks + buf*KS_SZ;
            const unsigned* Vbuf = Vs + buf*VS_SZ;

            // ---- S = Q K^T (16 x 32 per warp) ----
            float s[4][4];
            #pragma unroll
            for (int j = 0; j < 4; j++) {
                float sc[4] = {0.f, 0.f, 0.f, 0.f};
                const unsigned* kr = Kbuf + (j*8+gid)*KS_STRIDE;
                #pragma unroll
                for (int kc = 0; kc < 8; kc++)
                    mma8(sc, aq[kc], kr[kc*8 + tig], kr[kc*8 + tig + 4]);
                s[j][0] = sc[0]; s[j][1] = sc[1]; s[j][2] = sc[2]; s[j][3] = sc[3];
            }
            // causal mask (tiles straddling the diagonal)
            if (k0 + KT - 1 > wrow_min) {
                #pragma unroll
                for (int j = 0; j < 4; j++) {
                    int c0 = k0 + j*8 + 2*tig;
                    if (c0     > row_r ) s[j][0] = -1e30f;
                    if (c0 + 1 > row_r ) s[j][1] = -1e30f;
                    if (c0     > row_r8) s[j][2] = -1e30f;
                    if (c0 + 1 > row_r8) s[j][3] = -1e30f;
                }
            }
            // ---- online softmax (rows in 4-lane quads) ----
            float mx_r = -1e30f, mx_r8 = -1e30f;
            #pragma unroll
            for (int j = 0; j < 4; j++) {
                mx_r  = fmaxf(mx_r,  fmaxf(s[j][0], s[j][1]));
                mx_r8 = fmaxf(mx_r8, fmaxf(s[j][2], s[j][3]));
            }
            mx_r  = fmaxf(mx_r,  __shfl_xor_sync(0xffffffffu, mx_r,  1));
            mx_r  = fmaxf(mx_r,  __shfl_xor_sync(0xffffffffu, mx_r,  2));
            mx_r8 = fmaxf(mx_r8, __shfl_xor_sync(0xffffffffu, mx_r8, 1));
            mx_r8 = fmaxf(mx_r8, __shfl_xor_sync(0xffffffffu, mx_r8, 2));
            float mn_r  = fmaxf(m_r,  mx_r);
            float mn_r8 = fmaxf(m_r8, mx_r8);
            float corr_r  = __expf(m_r  - mn_r);
            float corr_r8 = __expf(m_r8 - mn_r8);
            m_r = mn_r; m_r8 = mn_r8;

            float ps_r = 0.0f, ps_r8 = 0.0f;
            unsigned pu[4][4];
            #pragma unroll
            for (int j = 0; j < 4; j++) {
                float p0 = __expf(s[j][0] - m_r);
                float p1 = __expf(s[j][1] - m_r);
                float p2 = __expf(s[j][2] - m_r8);
                float p3 = __expf(s[j][3] - m_r8);
                ps_r  += p0 + p1;
                ps_r8 += p2 + p3;
                pu[j][0] = f2tf(p0); pu[j][1] = f2tf(p1);
                pu[j][2] = f2tf(p2); pu[j][3] = f2tf(p3);
            }
            ps_r  += __shfl_xor_sync(0xffffffffu, ps_r,  1);
            ps_r  += __shfl_xor_sync(0xffffffffu, ps_r,  2);
            ps_r8 += __shfl_xor_sync(0xffffffffu, ps_r8, 1);
            ps_r8 += __shfl_xor_sync(0xffffffffu, ps_r8, 2);
            l_r  = l_r  * corr_r  + ps_r;
            l_r8 = l_r8 * corr_r8 + ps_r8;
            #pragma unroll
            for (int jd = 0; jd < 8; jd++) {
                oc[jd][0] *= corr_r;  oc[jd][1] *= corr_r;
                oc[jd][2] *= corr_r8; oc[jd][3] *= corr_r8;
            }

            // ---- O += P V : C-layout -> A-layout via quad shuffles ----
            const int srcA = (gid << 2) + (tig >> 1);
            const int srcB = srcA + 2;
            const bool odd = (tig & 1);
            #pragma unroll
            for (int j = 0; j < 4; j++) {
                unsigned q0A = __shfl_sync(0xffffffffu, pu[j][0], srcA);
                unsigned q1A = __shfl_sync(0xffffffffu, pu[j][1], srcA);
                unsigned q2A = __shfl_sync(0xffffffffu, pu[j][2], srcA);
                unsigned q3A = __shfl_sync(0xffffffffu, pu[j][3], srcA);
                unsigned q0B = __shfl_sync(0xffffffffu, pu[j][0], srcB);
                unsigned q1B = __shfl_sync(0xffffffffu, pu[j][1], srcB);
                unsigned q2B = __shfl_sync(0xffffffffu, pu[j][2], srcB);
                unsigned q3B = __shfl_sync(0xffffffffu, pu[j][3], srcB);
                unsigned ap[4];
                ap[0] = odd ? q1A : q0A;
                ap[1] = odd ? q3A : q2A;
                ap[2] = odd ? q1B : q0B;
                ap[3] = odd ? q3B : q2B;
                #pragma unroll
                for (int jd = 0; jd < 8; jd++)
                    mma8(oc[jd], ap,
                         Vbuf[(j*8+tig  )*VS_STRIDE + jd*8 + gid],
                         Vbuf[(j*8+tig+4)*VS_STRIDE + jd*8 + gid]);
            }
        }
        __syncthreads();
    }

    // ---- epilogue: normalize, convert, store tf32 to [b*n][h*64+d] ----
    float inv_r = 1.0f / l_r, inv_r8 = 1.0f / l_r8;
    unsigned* o0 = g_attn + ((size_t)(b*N_ + row_r )*INNER + h*DH_);
    unsigned* o1 = g_attn + ((size_t)(b*N_ + row_r8)*INNER + h*DH_);
    #pragma unroll
    for (int jd = 0; jd < 8; jd++) {
        int c = jd*8 + 2*tig;
        *(uint2*)&o0[c] = make_uint2(f2tf(oc[jd][0]*inv_r ), f2tf(oc[jd][1]*inv_r ));
        *(uint2*)&o1[c] = make_uint2(f2tf(oc[jd][2]*inv_r8), f2tf(oc[jd][3]*inv_r8));
    }
}

// =====================================================================
// Kernel 3: out = g_attn[8192,512] @ Wo[512,512] + bo
// =====================================================================
__global__ __launch_bounds__(256, 2) void out_mma_kernel(
    const float* __restrict__ bo, float* __restrict__ out)
{
    __shared__ unsigned As[2*AS_SZ];
    __shared__ unsigned Bs[2*BS_SZ];

    const int bx = blockIdx.x;   // 0..3
    const int by = blockIdx.y;   // 0..63
    const int row0 = by * 128;
    const int wcol = bx * 128;

    float acc[4][4][4];
    gemm_tf32_db(g_attn, g_Wo, 512, wcol, row0, acc, As, Bs);

    const int lane = threadIdx.x & 31, w = threadIdx.x >> 5;
    const int gid = lane >> 2, tig = lane & 3;
    const int m0w = (w >> 2) * 64, n0w = (w & 3) * 32;

    #pragma unroll
    for (int mt = 0; mt < 4; mt++) {
        int r0 = row0 + m0w + mt*16 + gid;
        int r1 = r0 + 8;
        #pragma unroll
        for (int nt = 0; nt < 4; nt++) {
            int c = wcol + n0w + nt*8 + 2*tig;
            float2 bias = *(const float2*)&bo[c];
            float2 v0 = make_float2(acc[mt][nt][0] + bias.x, acc[mt][nt][1] + bias.y);
            float2 v1 = make_float2(acc[mt][nt][2] + bias.x, acc[mt][nt][3] + bias.y);
            *(float2*)&out[(size_t)r0*512 + c] = v0;
            *(float2*)&out[(size_t)r1*512 + c] = v1;
        }
    }
}

// =====================================================================
extern "C" void kernel_launch(void* const* d_in, const int* in_sizes, int n_in,
                              void* d_out, int out_size)
{
    const float* x   = (const float*)d_in[0];
    const float* Wq  = (const float*)d_in[1];
    const float* Wkv = (const float*)d_in[2];
    const float* Wo  = (const float*)d_in[3];
    const float* bo  = (const float*)d_in[4];
    float* out = (float*)d_out;

    unsigned *p_x, *p_Wq, *p_Wkv, *p_Wo;
    cudaGetSymbolAddress((void**)&p_x,   g_x);
    cudaGetSymbolAddress((void**)&p_Wq,  g_Wq);
    cudaGetSymbolAddress((void**)&p_Wkv, g_Wkv);
    cudaGetSymbolAddress((void**)&p_Wo,  g_Wo);

    cvt_tf32_kernel<<<(BN_*DIM_/4 + 255)/256, 256>>>((const float4*)x,   (uint4*)p_x,   BN_*DIM_/4);
    cvt_tf32_kernel<<<(DIM_*INNER/4 + 255)/256, 256>>>((const float4*)Wq,  (uint4*)p_Wq,  DIM_*INNER/4);
    cvt_tf32_kernel<<<(DIM_*2*INNER/4 + 255)/256, 256>>>((const float4*)Wkv, (uint4*)p_Wkv, DIM_*2*INNER/4);
    cvt_tf32_kernel<<<(INNER*DIM_/4 + 255)/256, 256>>>((const float4*)Wo,  (uint4*)p_Wo,  INNER*DIM_/4);

    qkv_mma_kernel<<<dim3(12, 64), 256>>>();
    flash_mma_kernel<<<dim3(32, B_*H_), 256>>>();
    out_mma_kernel<<<dim3(4, 64), 256>>>(bo, out);
}

// round 6
// speedup vs baseline: 4.2409x; 1.1995x over previous
#include <cuda_runtime.h>
#include <cuda_fp16.h>

// Problem constants
#define B_    2
#define N_    4096
#define DIM_  512
#define H_    8
#define DH_   64
#define BN_   (B_*N_)          // 8192 rows
#define INNER (H_*DH_)         // 512

// ---------------- scratch (device globals; no runtime alloc) ----------------
__device__ __half g_x  [BN_*DIM_];         // x as fp16, [row][k]
__device__ __half g_WT [(3*INNER)*DIM_];   // [c][k]: 0..511 Wq cols, 512..1023 K, 1024..1535 V
__device__ __half g_WoT[DIM_*INNER];       // [n][k]
__device__ __half g_Q  [B_*H_*N_*DH_];     // [b][h][n][d], pre-scaled 1/64
__device__ __half g_K  [B_*H_*N_*DH_];
__device__ __half g_V  [B_*H_*N_*DH_];
__device__ __half g_attn[BN_*INNER];       // [b*n][h*DH+d]

// ---------------- helpers ----------------
__device__ __forceinline__ void mmaf16(float* c, unsigned a0, unsigned a1,
                                       unsigned a2, unsigned a3,
                                       unsigned b0, unsigned b1) {
    asm("mma.sync.aligned.m16n8k16.row.col.f32.f16.f16.f32 "
        "{%0,%1,%2,%3}, {%4,%5,%6,%7}, {%8,%9}, {%0,%1,%2,%3};"
        : "+f"(c[0]), "+f"(c[1]), "+f"(c[2]), "+f"(c[3])
        : "r"(a0), "r"(a1), "r"(a2), "r"(a3), "r"(b0), "r"(b1));
}
__device__ __forceinline__ void cpa16(void* smem_dst, const void* gsrc) {
    unsigned s = (unsigned)__cvta_generic_to_shared(smem_dst);
    asm volatile("cp.async.cg.shared.global [%0], [%1], 16;" :: "r"(s), "l"(gsrc));
}
__device__ __forceinline__ void cpa_commit() { asm volatile("cp.async.commit_group;"); }
template<int NN> __device__ __forceinline__ void cpa_wait() {
    asm volatile("cp.async.wait_group %0;" :: "n"(NN));
}
__device__ __forceinline__ void ldsm4t(unsigned& r0, unsigned& r1,
                                       unsigned& r2, unsigned& r3, unsigned addr) {
    asm volatile("ldmatrix.sync.aligned.m8n8.x4.trans.shared.b16 {%0,%1,%2,%3}, [%4];"
        : "=r"(r0), "=r"(r1), "=r"(r2), "=r"(r3) : "r"(addr));
}
__device__ __forceinline__ unsigned h2u(__half2 h) {
    return *(unsigned*)&h;
}

// =====================================================================
// Pre-pass kernels: fp32 -> fp16 (x), and transpose+convert (weights)
// =====================================================================
__global__ void cvt_h_kernel(const float4* __restrict__ src,
                             uint2* __restrict__ dst, int n4)
{
    int i = blockIdx.x * blockDim.x + threadIdx.x;
    if (i < n4) {
        float4 v = src[i];
        uint2 o;
        o.x = h2u(__floats2half2_rn(v.x, v.y));
        o.y = h2u(__floats2half2_rn(v.z, v.w));
        dst[i] = o;
    }
}

// dst[(rowoff + c)][k] = fp16(src[k][c]) ; src is [512][ldsrc]
__global__ void transp_cvt_kernel(const float* __restrict__ src, int ldsrc,
                                  __half* __restrict__ dst, int rowoff)
{
    __shared__ float s[32][33];
    int c0 = blockIdx.x * 32, k0 = blockIdx.y * 32;
    int tx = threadIdx.x, ty = threadIdx.y;   // (32, 8)
    #pragma unroll
    for (int i = 0; i < 32; i += 8)
        s[ty + i][tx] = src[(size_t)(k0 + ty + i) * ldsrc + c0 + tx];
    __syncthreads();
    #pragma unroll
    for (int i = 0; i < 32; i += 8)
        dst[(size_t)(rowoff + c0 + ty + i) * 512 + k0 + tx] = __float2half_rn(s[tx][ty + i]);
}

// =====================================================================
// fp16 GEMM core: C[128x128] = A[row0..,512] * (W[bcol0..,512])^T
// Both operands K-major fp16. 256 thr / 8 warps, warp tile 64x32.
// Smem: [row][k-half2] stride 20 half2 (16 used + 4 pad), K-chunks of 32.
// =====================================================================
#define GS 20               // half2 stride
#define GTILE (128*GS)      // 2560 half2 per tile buffer

__device__ __forceinline__ void gemm_stage(const __half* __restrict__ A,
                                           const __half* __restrict__ W,
                                           int row0, int bcol0, int k0,
                                           unsigned* As, unsigned* Bs, int tid)
{
    #pragma unroll
    for (int i = 0; i < 2; i++) {
        int idx = tid + i*256;              // 0..511
        int r = idx >> 2, seg = idx & 3;
        cpa16(&As[r*GS + seg*4], &A[(size_t)(row0  + r)*512 + k0 + seg*8]);
        cpa16(&Bs[r*GS + seg*4], &W[(size_t)(bcol0 + r)*512 + k0 + seg*8]);
    }
}

__device__ __forceinline__ void gemm_f16(const __half* __restrict__ A,
                                         const __half* __restrict__ W,
                                         int row0, int bcol0,
                                         float (&acc)[4][4][4],
                                         unsigned* AsBuf, unsigned* BsBuf)
{
    const int tid  = threadIdx.x;
    const int lane = tid & 31, w = tid >> 5;
    const int gid  = lane >> 2, tig = lane & 3;
    const int m0w  = (w >> 2) * 64;
    const int n0w  = (w & 3) * 32;

    #pragma unroll
    for (int mt = 0; mt < 4; mt++)
        #pragma unroll
        for (int nt = 0; nt < 4; nt++)
            #pragma unroll
            for (int r = 0; r < 4; r++) acc[mt][nt][r] = 0.0f;

    gemm_stage(A, W, row0, bcol0, 0, AsBuf, BsBuf, tid);
    cpa_commit();

    for (int it = 0; it < 16; it++) {
        const int buf = it & 1;
        if (it + 1 < 16) {
            gemm_stage(A, W, row0, bcol0, (it+1)*32,
                       AsBuf + (buf^1)*GTILE, BsBuf + (buf^1)*GTILE, tid);
            cpa_commit();
            cpa_wait<1>();
        } else {
            cpa_wait<0>();
        }
        __syncthreads();

        const unsigned* As = AsBuf + buf*GTILE;
        const unsigned* Bs = BsBuf + buf*GTILE;
        #pragma unroll
        for (int kc = 0; kc < 2; kc++) {
            const int kk = kc * 8;
            unsigned am[4][4];
            #pragma unroll
            for (int mt = 0; mt < 4; mt++) {
                int mr = m0w + mt*16;
                am[mt][0] = As[(mr+gid  )*GS + kk + tig    ];
                am[mt][1] = As[(mr+gid+8)*GS + kk + tig    ];
                am[mt][2] = As[(mr+gid  )*GS + kk + tig + 4];
                am[mt][3] = As[(mr+gid+8)*GS + kk + tig + 4];
            }
            unsigned bn[4][2];
            #pragma unroll
            for (int nt = 0; nt < 4; nt++) {
                bn[nt][0] = Bs[(n0w+nt*8+gid)*GS + kk + tig    ];
                bn[nt][1] = Bs[(n0w+nt*8+gid)*GS + kk + tig + 4];
            }
            #pragma unroll
            for (int mt = 0; mt < 4; mt++)
                #pragma unroll
                for (int nt = 0; nt < 4; nt++)
                    mmaf16(acc[mt][nt], am[mt][0], am[mt][1], am[mt][2], am[mt][3],
                           bn[nt][0], bn[nt][1]);
        }
        __syncthreads();
    }
}

// ---- Kernel 1: QKV projection, scatter fp16 to [B,H,N,DH] (Q * 1/64) ----
__global__ __launch_bounds__(256, 2) void qkv_f16_kernel()
{
    __shared__ unsigned As[2*GTILE];
    __shared__ unsigned Bs[2*GTILE];

    const int bx = blockIdx.x;       // 0..11
    const int row0 = blockIdx.y * 128;
    const int which = bx >> 2;       // 0 Q, 1 K, 2 V
    const int bcol0 = bx * 128;
    const int lcolbase = (bx & 3) * 128;

    float acc[4][4][4];
    gemm_f16(g_x, g_WT, row0, bcol0, acc, As, Bs);

    const float scale = (which == 0) ? (1.0f/64.0f) : 1.0f;
    __half* dst = (which == 0) ? g_Q : (which == 1 ? g_K : g_V);

    const int lane = threadIdx.x & 31, w = threadIdx.x >> 5;
    const int gid = lane >> 2, tig = lane & 3;
    const int m0w = (w >> 2) * 64, n0w = (w & 3) * 32;

    #pragma unroll
    for (int mt = 0; mt < 4; mt++) {
        int r0 = row0 + m0w + mt*16 + gid;
        int r1 = r0 + 8;
        int b0i = r0 >> 12, n0i = r0 & (N_-1);
        int b1i = r1 >> 12, n1i = r1 & (N_-1);
        #pragma unroll
        for (int nt = 0; nt < 4; nt++) {
            int c = lcolbase + n0w + nt*8 + 2*tig;
            int h = c >> 6, d = c & 63;
            __half2 v0 = __floats2half2_rn(acc[mt][nt][0]*scale, acc[mt][nt][1]*scale);
            __half2 v1 = __floats2half2_rn(acc[mt][nt][2]*scale, acc[mt][nt][3]*scale);
            *(__half2*)&dst[(((size_t)(b0i*H_ + h)*N_ + n0i)*DH_ + d)] = v0;
            *(__half2*)&dst[(((size_t)(b1i*H_ + h)*N_ + n1i)*DH_ + d)] = v1;
        }
    }
}

// ---- Kernel 3: out = g_attn @ WoT^T + bo ----
__global__ __launch_bounds__(256, 2) void out_f16_kernel(
    const float* __restrict__ bo, float* __restrict__ out)
{
    __shared__ unsigned As[2*GTILE];
    __shared__ unsigned Bs[2*GTILE];

    const int row0 = blockIdx.y * 128;
    const int wcol = blockIdx.x * 128;

    float acc[4][4][4];
    gemm_f16(g_attn, g_WoT, row0, wcol, acc, As, Bs);

    const int lane = threadIdx.x & 31, w = threadIdx.x >> 5;
    const int gid = lane >> 2, tig = lane & 3;
    const int m0w = (w >> 2) * 64, n0w = (w & 3) * 32;

    #pragma unroll
    for (int mt = 0; mt < 4; mt++) {
        int r0 = row0 + m0w + mt*16 + gid;
        int r1 = r0 + 8;
        #pragma unroll
        for (int nt = 0; nt < 4; nt++) {
            int c = wcol + n0w + nt*8 + 2*tig;
            float2 bias = *(const float2*)&bo[c];
            float2 v0 = make_float2(acc[mt][nt][0] + bias.x, acc[mt][nt][1] + bias.y);
            float2 v1 = make_float2(acc[mt][nt][2] + bias.x, acc[mt][nt][3] + bias.y);
            *(float2*)&out[(size_t)r0*512 + c] = v0;
            *(float2*)&out[(size_t)r1*512 + c] = v1;
        }
    }
}

// =====================================================================
// Kernel 2: causal flash attention, fp16 mma.
//   256 threads / 8 warps, 128 q-rows (16/warp), K/V tiles of 32 (db).
//   P C-layout == A-layout (no shuffles); V B-frags via ldmatrix.x4.trans.
// =====================================================================
#define FS 36               // half2 stride for Q/K/V smem rows (32 used + 4 pad)
#define KVT (32*FS)         // 1152 half2 per K or V tile buffer

__global__ __launch_bounds__(256, 2) void flash_f16_kernel()
{
    __shared__ unsigned Qs[128*FS];     // 18.4 KB
    __shared__ unsigned Ks[2*KVT];      // 9.2 KB
    __shared__ unsigned Vs[2*KVT];      // 9.2 KB

    const int bh = blockIdx.y, b = bh >> 3, h = bh & 7;
    const int tile = 31 - (int)blockIdx.x;
    const int tid = threadIdx.x, lane = tid & 31, w = tid >> 5;
    const int gid = lane >> 2, tig = lane & 3;

    const __half* Qb = g_Q + (size_t)bh * N_ * DH_;
    const __half* Kb = g_K + (size_t)bh * N_ * DH_;
    const __half* Vb = g_V + (size_t)bh * N_ * DH_;
    const int qrow0 = tile * 128;

    // ---- stage Q tile (128 x 64 halves) ----
    #pragma unroll
    for (int i = 0; i < 4; i++) {
        int idx = tid + i*256;              // 0..1023
        int rr = idx >> 3, seg = idx & 7;
        cpa16(&Qs[rr*FS + seg*4], &Qb[(size_t)(qrow0+rr)*DH_ + seg*8]);
    }
    cpa_commit(); cpa_wait<0>();
    __syncthreads();
    unsigned aq[4][4];
    {
        const unsigned* Qw = Qs + (16*w)*FS;
        #pragma unroll
        for (int c = 0; c < 4; c++) {
            aq[c][0] = Qw[(gid  )*FS + c*8 + tig    ];
            aq[c][1] = Qw[(gid+8)*FS + c*8 + tig    ];
            aq[c][2] = Qw[(gid  )*FS + c*8 + tig + 4];
            aq[c][3] = Qw[(gid+8)*FS + c*8 + tig + 4];
        }
    }

    float oc[8][4];
    #pragma unroll
    for (int jd = 0; jd < 8; jd++)
        #pragma unroll
        for (int r = 0; r < 4; r++) oc[jd][r] = 0.0f;
    float m_r = -1e30f, m_r8 = -1e30f, l_r = 0.0f, l_r8 = 0.0f;
    const int wrow_min = qrow0 + 16*w;
    const int row_r = wrow_min + gid, row_r8 = row_r + 8;

    const int nkt = (qrow0 + 128) / 32;     // 4*(tile+1)

    // stage first K/V tile (32 x 64 halves each)
    {
        int rr = tid >> 3, seg = tid & 7;   // 256 threads exactly cover one array
        cpa16(&Ks[rr*FS + seg*4], &Kb[(size_t)rr*DH_ + seg*8]);
        cpa16(&Vs[rr*FS + seg*4], &Vb[(size_t)rr*DH_ + seg*8]);
    }
    cpa_commit();

    for (int kt = 0; kt < nkt; kt++) {
        const int k0 = kt * 32;
        const int buf = kt & 1;
        if (kt + 1 < nkt) {
            const int kn = k0 + 32;
            int rr = tid >> 3, seg = tid & 7;
            cpa16(&Ks[(buf^1)*KVT + rr*FS + seg*4], &Kb[(size_t)(kn+rr)*DH_ + seg*8]);
            cpa16(&Vs[(buf^1)*KVT + rr*FS + seg*4], &Vb[(size_t)(kn+rr)*DH_ + seg*8]);
            cpa_commit();
            cpa_wait<1>();
        } else {
            cpa_wait<0>();
        }
        __syncthreads();

        const bool active = (k0 <= wrow_min + 15);   // warp-uniform
        if (active) {
            const unsigned* Kbuf = Ks + buf*KVT;
            const unsigned* Vbuf = Vs + buf*KVT;

            // ---- S = Q K^T (16 x 32 per warp) ----
            float s[4][4];
            #pragma unroll
            for (int j = 0; j < 4; j++) {
                float sc[4] = {0.f, 0.f, 0.f, 0.f};
                const unsigned* kr = Kbuf + (j*8+gid)*FS;
                #pragma unroll
                for (int c = 0; c < 4; c++)
                    mmaf16(sc, aq[c][0], aq[c][1], aq[c][2], aq[c][3],
                           kr[c*8 + tig], kr[c*8 + tig + 4]);
                s[j][0] = sc[0]; s[j][1] = sc[1]; s[j][2] = sc[2]; s[j][3] = sc[3];
            }
            // causal mask (tiles straddling the diagonal)
            if (k0 + 31 > wrow_min) {
                #pragma unroll
                for (int j = 0; j < 4; j++) {
                    int c0 = k0 + j*8 + 2*tig;
                    if (c0     > row_r ) s[j][0] = -1e30f;
                    if (c0 + 1 > row_r ) s[j][1] = -1e30f;
                    if (c0     > row_r8) s[j][2] = -1e30f;
                    if (c0 + 1 > row_r8) s[j][3] = -1e30f;
                }
            }
            // ---- online softmax (rows in 4-lane quads) ----
            float mx_r = -1e30f, mx_r8 = -1e30f;
            #pragma unroll
            for (int j = 0; j < 4; j++) {
                mx_r  = fmaxf(mx_r,  fmaxf(s[j][0], s[j][1]));
                mx_r8 = fmaxf(mx_r8, fmaxf(s[j][2], s[j][3]));
            }
            mx_r  = fmaxf(mx_r,  __shfl_xor_sync(0xffffffffu, mx_r,  1));
            mx_r  = fmaxf(mx_r,  __shfl_xor_sync(0xffffffffu, mx_r,  2));
            mx_r8 = fmaxf(mx_r8, __shfl_xor_sync(0xffffffffu, mx_r8, 1));
            mx_r8 = fmaxf(mx_r8, __shfl_xor_sync(0xffffffffu, mx_r8, 2));
            float mn_r  = fmaxf(m_r,  mx_r);
            float mn_r8 = fmaxf(m_r8, mx_r8);
            float corr_r  = __expf(m_r  - mn_r);
            float corr_r8 = __expf(m_r8 - mn_r8);
            m_r = mn_r; m_r8 = mn_r8;

            float ps_r = 0.0f, ps_r8 = 0.0f;
            unsigned ap[2][4];    // P as fp16 A-fragments, chunk c covers keys 16c..16c+15
            #pragma unroll
            for (int j = 0; j < 4; j++) {
                float p0 = __expf(s[j][0] - m_r);
                float p1 = __expf(s[j][1] - m_r);
                float p2 = __expf(s[j][2] - m_r8);
                float p3 = __expf(s[j][3] - m_r8);
                ps_r  += p0 + p1;
                ps_r8 += p2 + p3;
                int c = j >> 1, hi = j & 1;       // j-block -> (chunk, k-lo/k-hi)
                ap[c][hi*2    ] = h2u(__floats2half2_rn(p0, p1));   // row gid
                ap[c][hi*2 + 1] = h2u(__floats2half2_rn(p2, p3));   // row gid+8
            }
            // reorder: fragment order is {row-lo k-lo, row-hi k-lo, row-lo k-hi, row-hi k-hi}
            // ap[c] currently {rl-kl, rh-kl, rl-kh, rh-kh} -> already correct.
            ps_r  += __shfl_xor_sync(0xffffffffu, ps_r,  1);
            ps_r  += __shfl_xor_sync(0xffffffffu, ps_r,  2);
            ps_r8 += __shfl_xor_sync(0xffffffffu, ps_r8, 1);
            ps_r8 += __shfl_xor_sync(0xffffffffu, ps_r8, 2);
            l_r  = l_r  * corr_r  + ps_r;
            l_r8 = l_r8 * corr_r8 + ps_r8;
            #pragma unroll
            for (int jd = 0; jd < 8; jd++) {
                oc[jd][0] *= corr_r;  oc[jd][1] *= corr_r;
                oc[jd][2] *= corr_r8; oc[jd][3] *= corr_r8;
            }

            // ---- O += P V ; V B-frags via ldmatrix.x4.trans ----
            const int lrow = lane & 15;           // key row within chunk
            const int lcol8 = (lane & 16) ? 8 : 0;
            #pragma unroll
            for (int c = 0; c < 2; c++) {
                #pragma unroll
                for (int jd2 = 0; jd2 < 4; jd2++) {
                    unsigned addr = (unsigned)__cvta_generic_to_shared(
                        (const char*)(Vbuf + (c*16 + lrow)*FS + jd2*8) + lcol8*2);
                    unsigned r0, r1, r2, r3;
                    ldsm4t(r0, r1, r2, r3, addr);
                    mmaf16(oc[2*jd2    ], ap[c][0], ap[c][1], ap[c][2], ap[c][3], r0, r1);
                    mmaf16(oc[2*jd2 + 1], ap[c][0], ap[c][1], ap[c][2], ap[c][3], r2, r3);
                }
            }
        }
        __syncthreads();
    }

    // ---- epilogue: normalize, store fp16 to [b*n][h*64+d] ----
    float inv_r = 1.0f / l_r, inv_r8 = 1.0f / l_r8;
    __half* o0 = g_attn + ((size_t)(b*N_ + row_r )*INNER + h*DH_);
    __half* o1 = g_attn + ((size_t)(b*N_ + row_r8)*INNER + h*DH_);
    #pragma unroll
    for (int jd = 0; jd < 8; jd++) {
        int c = jd*8 + 2*tig;
        *(__half2*)&o0[c] = __floats2half2_rn(oc[jd][0]*inv_r,  oc[jd][1]*inv_r );
        *(__half2*)&o1[c] = __floats2half2_rn(oc[jd][2]*inv_r8, oc[jd][3]*inv_r8);
    }
}

// =====================================================================
extern "C" void kernel_launch(void* const* d_in, const int* in_sizes, int n_in,
                              void* d_out, int out_size)
{
    const float* x   = (const float*)d_in[0];
    const float* Wq  = (const float*)d_in[1];
    const float* Wkv = (const float*)d_in[2];
    const float* Wo  = (const float*)d_in[3];
    const float* bo  = (const float*)d_in[4];
    float* out = (float*)d_out;

    __half *p_x, *p_WT, *p_WoT;
    cudaGetSymbolAddress((void**)&p_x,   g_x);
    cudaGetSymbolAddress((void**)&p_WT,  g_WT);
    cudaGetSymbolAddress((void**)&p_WoT, g_WoT);

    // pre-pass: x -> fp16 ; weights -> fp16 transposed K-major
    cvt_h_kernel<<<(BN_*DIM_/4 + 255)/256, 256>>>((const float4*)x, (uint2*)p_x, BN_*DIM_/4);
    transp_cvt_kernel<<<dim3(512/32, 16),  dim3(32,8)>>>(Wq,  512,  p_WT, 0);
    transp_cvt_kernel<<<dim3(1024/32, 16), dim3(32,8)>>>(Wkv, 1024, p_WT, 512);
    transp_cvt_kernel<<<dim3(512/32, 16),  dim3(32,8)>>>(Wo,  512,  p_WoT, 0);

    qkv_f16_kernel<<<dim3(12, 64), 256>>>();
    flash_f16_kernel<<<dim3(32, B_*H_), 256>>>();
    out_f16_kernel<<<dim3(4, 64), 256>>>(bo, out);
}

// round 7
// speedup vs baseline: 6.9658x; 1.6425x over previous
#include <cuda_runtime.h>
#include <cuda_fp16.h>

// Problem constants
#define B_    2
#define N_    4096
#define DIM_  512
#define H_    8
#define DH_   64
#define BN_   (B_*N_)          // 8192 rows
#define INNER (H_*DH_)         // 512

// ---------------- scratch (device globals; no runtime alloc) ----------------
__device__ __half g_x  [BN_*DIM_];         // x as fp16, [row][k]
__device__ __half g_WT [(3*INNER)*DIM_];   // [c][k]: 0..511 Wq cols, 512..1023 K, 1024..1535 V
__device__ __half g_WoT[DIM_*INNER];       // [n][k]
__device__ __half g_Q  [B_*H_*N_*DH_];     // [b][h][n][d], pre-scaled (1/64)*log2e
__device__ __half g_K  [B_*H_*N_*DH_];
__device__ __half g_V  [B_*H_*N_*DH_];
__device__ __half g_attn[BN_*INNER];       // [b*n][h*DH+d]

// ---------------- helpers ----------------
__device__ __forceinline__ void mmaf16(float* c, unsigned a0, unsigned a1,
                                       unsigned a2, unsigned a3,
                                       unsigned b0, unsigned b1) {
    asm("mma.sync.aligned.m16n8k16.row.col.f32.f16.f16.f32 "
        "{%0,%1,%2,%3}, {%4,%5,%6,%7}, {%8,%9}, {%0,%1,%2,%3};"
        : "+f"(c[0]), "+f"(c[1]), "+f"(c[2]), "+f"(c[3])
        : "r"(a0), "r"(a1), "r"(a2), "r"(a3), "r"(b0), "r"(b1));
}
__device__ __forceinline__ void cpa16(void* smem_dst, const void* gsrc) {
    unsigned s = (unsigned)__cvta_generic_to_shared(smem_dst);
    asm volatile("cp.async.cg.shared.global [%0], [%1], 16;" :: "r"(s), "l"(gsrc));
}
__device__ __forceinline__ void cpa_commit() { asm volatile("cp.async.commit_group;"); }
template<int NN> __device__ __forceinline__ void cpa_wait() {
    asm volatile("cp.async.wait_group %0;" :: "n"(NN));
}
__device__ __forceinline__ void ldsm4t(unsigned& r0, unsigned& r1,
                                       unsigned& r2, unsigned& r3, unsigned addr) {
    asm volatile("ldmatrix.sync.aligned.m8n8.x4.trans.shared.b16 {%0,%1,%2,%3}, [%4];"
        : "=r"(r0), "=r"(r1), "=r"(r2), "=r"(r3) : "r"(addr));
}
__device__ __forceinline__ unsigned h2u(__half2 h) { return *(unsigned*)&h; }
__device__ __forceinline__ float ex2f(float x) {      // raw exp2
    float r; asm("ex2.approx.f32 %0, %1;" : "=f"(r) : "f"(x)); return r;
}

// =====================================================================
// Pre-pass kernels
// =====================================================================
__global__ void cvt_h_kernel(const float4* __restrict__ src,
                             uint2* __restrict__ dst, int n4)
{
    int i = blockIdx.x * blockDim.x + threadIdx.x;
    if (i < n4) {
        float4 v = src[i];
        uint2 o;
        o.x = h2u(__floats2half2_rn(v.x, v.y));
        o.y = h2u(__floats2half2_rn(v.z, v.w));
        dst[i] = o;
    }
}

// Fused weight transpose+convert: one launch for Wq | Wkv | Wo.
// grid (64, 16): bx<16 -> Wq (cols 0..511 -> WT rows 0..511)
//                bx<48 -> Wkv (cols -> WT rows 512..1535)
//                else  -> Wo  (cols -> WoT rows 0..511)
__global__ void transp_all_kernel(const float* __restrict__ Wq,
                                  const float* __restrict__ Wkv,
                                  const float* __restrict__ Wo)
{
    __shared__ float s[32][33];
    const int bx = blockIdx.x;
    const float* src; int ldsrc, cg; __half* dst;
    if (bx < 16)      { src = Wq;  ldsrc = 512;  cg = bx;      dst = g_WT; }
    else if (bx < 48) { src = Wkv; ldsrc = 1024; cg = bx - 16; dst = g_WT + (size_t)512*DIM_; }
    else              { src = Wo;  ldsrc = 512;  cg = bx - 48; dst = g_WoT; }

    int c0 = cg * 32, k0 = blockIdx.y * 32;
    int tx = threadIdx.x, ty = threadIdx.y;   // (32, 8)
    #pragma unroll
    for (int i = 0; i < 32; i += 8)
        s[ty + i][tx] = src[(size_t)(k0 + ty + i) * ldsrc + c0 + tx];
    __syncthreads();
    #pragma unroll
    for (int i = 0; i < 32; i += 8)
        dst[(size_t)(c0 + ty + i) * 512 + k0 + tx] = __float2half_rn(s[tx][ty + i]);
}

// =====================================================================
// fp16 GEMM core: C[128x128] = A[row0..,512] * (W[bcol0..,512])^T
// =====================================================================
#define GS 20               // half2 stride
#define GTILE (128*GS)

__device__ __forceinline__ void gemm_stage(const __half* __restrict__ A,
                                           const __half* __restrict__ W,
                                           int row0, int bcol0, int k0,
                                           unsigned* As, unsigned* Bs, int tid)
{
    #pragma unroll
    for (int i = 0; i < 2; i++) {
        int idx = tid + i*256;
        int r = idx >> 2, seg = idx & 3;
        cpa16(&As[r*GS + seg*4], &A[(size_t)(row0  + r)*512 + k0 + seg*8]);
        cpa16(&Bs[r*GS + seg*4], &W[(size_t)(bcol0 + r)*512 + k0 + seg*8]);
    }
}

__device__ __forceinline__ void gemm_f16(const __half* __restrict__ A,
                                         const __half* __restrict__ W,
                                         int row0, int bcol0,
                                         float (&acc)[4][4][4],
                                         unsigned* AsBuf, unsigned* BsBuf)
{
    const int tid  = threadIdx.x;
    const int lane = tid & 31, w = tid >> 5;
    const int gid  = lane >> 2, tig = lane & 3;
    const int m0w  = (w >> 2) * 64;
    const int n0w  = (w & 3) * 32;

    #pragma unroll
    for (int mt = 0; mt < 4; mt++)
        #pragma unroll
        for (int nt = 0; nt < 4; nt++)
            #pragma unroll
            for (int r = 0; r < 4; r++) acc[mt][nt][r] = 0.0f;

    gemm_stage(A, W, row0, bcol0, 0, AsBuf, BsBuf, tid);
    cpa_commit();

    for (int it = 0; it < 16; it++) {
        const int buf = it & 1;
        if (it + 1 < 16) {
            gemm_stage(A, W, row0, bcol0, (it+1)*32,
                       AsBuf + (buf^1)*GTILE, BsBuf + (buf^1)*GTILE, tid);
            cpa_commit();
            cpa_wait<1>();
        } else {
            cpa_wait<0>();
        }
        __syncthreads();

        const unsigned* As = AsBuf + buf*GTILE;
        const unsigned* Bs = BsBuf + buf*GTILE;
        #pragma unroll
        for (int kc = 0; kc < 2; kc++) {
            const int kk = kc * 8;
            unsigned am[4][4];
            #pragma unroll
            for (int mt = 0; mt < 4; mt++) {
                int mr = m0w + mt*16;
                am[mt][0] = As[(mr+gid  )*GS + kk + tig    ];
                am[mt][1] = As[(mr+gid+8)*GS + kk + tig    ];
                am[mt][2] = As[(mr+gid  )*GS + kk + tig + 4];
                am[mt][3] = As[(mr+gid+8)*GS + kk + tig + 4];
            }
            unsigned bn[4][2];
            #pragma unroll
            for (int nt = 0; nt < 4; nt++) {
                bn[nt][0] = Bs[(n0w+nt*8+gid)*GS + kk + tig    ];
                bn[nt][1] = Bs[(n0w+nt*8+gid)*GS + kk + tig + 4];
            }
            #pragma unroll
            for (int mt = 0; mt < 4; mt++)
                #pragma unroll
                for (int nt = 0; nt < 4; nt++)
                    mmaf16(acc[mt][nt], am[mt][0], am[mt][1], am[mt][2], am[mt][3],
                           bn[nt][0], bn[nt][1]);
        }
        __syncthreads();
    }
}

// ---- Kernel 1: QKV projection, scatter fp16 to [B,H,N,DH] ----
// Q scaled by (1/64)*log2e so flash can use raw exp2.
#define QSCALE (1.44269504088896f / 64.0f)

__global__ __launch_bounds__(256, 2) void qkv_f16_kernel()
{
    __shared__ unsigned As[2*GTILE];
    __shared__ unsigned Bs[2*GTILE];

    const int bx = blockIdx.x;
    const int row0 = blockIdx.y * 128;
    const int which = bx >> 2;
    const int bcol0 = bx * 128;
    const int lcolbase = (bx & 3) * 128;

    float acc[4][4][4];
    gemm_f16(g_x, g_WT, row0, bcol0, acc, As, Bs);

    const float scale = (which == 0) ? QSCALE : 1.0f;
    __half* dst = (which == 0) ? g_Q : (which == 1 ? g_K : g_V);

    const int lane = threadIdx.x & 31, w = threadIdx.x >> 5;
    const int gid = lane >> 2, tig = lane & 3;
    const int m0w = (w >> 2) * 64, n0w = (w & 3) * 32;

    #pragma unroll
    for (int mt = 0; mt < 4; mt++) {
        int r0 = row0 + m0w + mt*16 + gid;
        int r1 = r0 + 8;
        int b0i = r0 >> 12, n0i = r0 & (N_-1);
        int b1i = r1 >> 12, n1i = r1 & (N_-1);
        #pragma unroll
        for (int nt = 0; nt < 4; nt++) {
            int c = lcolbase + n0w + nt*8 + 2*tig;
            int h = c >> 6, d = c & 63;
            __half2 v0 = __floats2half2_rn(acc[mt][nt][0]*scale, acc[mt][nt][1]*scale);
            __half2 v1 = __floats2half2_rn(acc[mt][nt][2]*scale, acc[mt][nt][3]*scale);
            *(__half2*)&dst[(((size_t)(b0i*H_ + h)*N_ + n0i)*DH_ + d)] = v0;
            *(__half2*)&dst[(((size_t)(b1i*H_ + h)*N_ + n1i)*DH_ + d)] = v1;
        }
    }
}

// ---- Kernel 3: out = g_attn @ WoT^T + bo ----
__global__ __launch_bounds__(256, 2) void out_f16_kernel(
    const float* __restrict__ bo, float* __restrict__ out)
{
    __shared__ unsigned As[2*GTILE];
    __shared__ unsigned Bs[2*GTILE];

    const int row0 = blockIdx.y * 128;
    const int wcol = blockIdx.x * 128;

    float acc[4][4][4];
    gemm_f16(g_attn, g_WoT, row0, wcol, acc, As, Bs);

    const int lane = threadIdx.x & 31, w = threadIdx.x >> 5;
    const int gid = lane >> 2, tig = lane & 3;
    const int m0w = (w >> 2) * 64, n0w = (w & 3) * 32;

    #pragma unroll
    for (int mt = 0; mt < 4; mt++) {
        int r0 = row0 + m0w + mt*16 + gid;
        int r1 = r0 + 8;
        #pragma unroll
        for (int nt = 0; nt < 4; nt++) {
            int c = wcol + n0w + nt*8 + 2*tig;
            float2 bias = *(const float2*)&bo[c];
            float2 v0 = make_float2(acc[mt][nt][0] + bias.x, acc[mt][nt][1] + bias.y);
            float2 v1 = make_float2(acc[mt][nt][2] + bias.x, acc[mt][nt][3] + bias.y);
            *(float2*)&out[(size_t)r0*512 + c] = v0;
            *(float2*)&out[(size_t)r1*512 + c] = v1;
        }
    }
}

// =====================================================================
// Kernel 2: causal flash attention, fp16 mma, KT=64, exp2 domain.
//   256 threads / 8 warps, 128 q-rows (16/warp), K/V tiles of 64 (db).
//   Smem reused: Q staged in the same region as the K/V double buffers.
// =====================================================================
#define FS 36               // half2 stride per row (32 used + 4 pad)
#define KVT (64*FS)         // 2304 half2 per K or V tile buffer

__global__ __launch_bounds__(256, 2) void flash_f16_kernel()
{
    __shared__ unsigned SMEM[4*KVT];    // 36.9 KB: [K0 K1 V0 V1]; Q staged at front
    unsigned* Ks = SMEM;
    unsigned* Vs = SMEM + 2*KVT;

    const int bh = blockIdx.y, b = bh >> 3, h = bh & 7;
    const int tile = 31 - (int)blockIdx.x;
    const int tid = threadIdx.x, lane = tid & 31, w = tid >> 5;
    const int gid = lane >> 2, tig = lane & 3;

    const __half* Qb = g_Q + (size_t)bh * N_ * DH_;
    const __half* Kb = g_K + (size_t)bh * N_ * DH_;
    const __half* Vb = g_V + (size_t)bh * N_ * DH_;
    const int qrow0 = tile * 128;

    // ---- stage Q tile (128 x 64 halves) into front of SMEM ----
    #pragma unroll
    for (int i = 0; i < 4; i++) {
        int idx = tid + i*256;              // 0..1023
        int rr = idx >> 3, seg = idx & 7;
        cpa16(&SMEM[rr*FS + seg*4], &Qb[(size_t)(qrow0+rr)*DH_ + seg*8]);
    }
    cpa_commit(); cpa_wait<0>();
    __syncthreads();
    unsigned aq[4][4];
    {
        const unsigned* Qw = SMEM + (16*w)*FS;
        #pragma unroll
        for (int c = 0; c < 4; c++) {
            aq[c][0] = Qw[(gid  )*FS + c*8 + tig    ];
            aq[c][1] = Qw[(gid+8)*FS + c*8 + tig    ];
            aq[c][2] = Qw[(gid  )*FS + c*8 + tig + 4];
            aq[c][3] = Qw[(gid+8)*FS + c*8 + tig + 4];
        }
    }
    __syncthreads();   // Q reads complete before K/V staging reuses the region

    float oc[8][4];
    #pragma unroll
    for (int jd = 0; jd < 8; jd++)
        #pragma unroll
        for (int r = 0; r < 4; r++) oc[jd][r] = 0.0f;
    float m_r = -1e30f, m_r8 = -1e30f, l_r = 0.0f, l_r8 = 0.0f;
    const int wrow_min = qrow0 + 16*w;
    const int row_r = wrow_min + gid, row_r8 = row_r + 8;

    const int nkt = (qrow0 + 128) / 64;     // 2*(tile+1)

    // stage first K/V tile (64 rows x 8 segs each = 512 cpa per array)
    #pragma unroll
    for (int i = 0; i < 2; i++) {
        int idx = tid + i*256;              // 0..511
        int rr = idx >> 3, seg = idx & 7;
        cpa16(&Ks[rr*FS + seg*4], &Kb[(size_t)rr*DH_ + seg*8]);
        cpa16(&Vs[rr*FS + seg*4], &Vb[(size_t)rr*DH_ + seg*8]);
    }
    cpa_commit();

    for (int kt = 0; kt < nkt; kt++) {
        const int k0 = kt * 64;
        const int buf = kt & 1;
        if (kt + 1 < nkt) {
            const int kn = k0 + 64;
            unsigned* Kd = Ks + (buf^1)*KVT;
            unsigned* Vd = Vs + (buf^1)*KVT;
            #pragma unroll
            for (int i = 0; i < 2; i++) {
                int idx = tid + i*256;
                int rr = idx >> 3, seg = idx & 7;
                cpa16(&Kd[rr*FS + seg*4], &Kb[(size_t)(kn+rr)*DH_ + seg*8]);
                cpa16(&Vd[rr*FS + seg*4], &Vb[(size_t)(kn+rr)*DH_ + seg*8]);
            }
            cpa_commit();
            cpa_wait<1>();
        } else {
            cpa_wait<0>();
        }
        __syncthreads();

        const bool active = (k0 <= wrow_min + 15);   // warp-uniform
        if (active) {
            const unsigned* Kbuf = Ks + buf*KVT;
            const unsigned* Vbuf = Vs + buf*KVT;

            // ---- S = Q K^T (16 x 64 per warp), log2-domain scores ----
            float s[8][4];
            #pragma unroll
            for (int j = 0; j < 8; j++) {
                float sc[4] = {0.f, 0.f, 0.f, 0.f};
                const unsigned* kr = Kbuf + (j*8+gid)*FS;
                #pragma unroll
                for (int c = 0; c < 4; c++)
                    mmaf16(sc, aq[c][0], aq[c][1], aq[c][2], aq[c][3],
                           kr[c*8 + tig], kr[c*8 + tig + 4]);
                s[j][0] = sc[0]; s[j][1] = sc[1]; s[j][2] = sc[2]; s[j][3] = sc[3];
            }
            // causal mask (tile straddles the diagonal)
            if (k0 + 63 > wrow_min) {
                #pragma unroll
                for (int j = 0; j < 8; j++) {
                    int c0 = k0 + j*8 + 2*tig;
                    if (c0     > row_r ) s[j][0] = -1e30f;
                    if (c0 + 1 > row_r ) s[j][1] = -1e30f;
                    if (c0     > row_r8) s[j][2] = -1e30f;
                    if (c0 + 1 > row_r8) s[j][3] = -1e30f;
                }
            }
            // ---- online softmax (exp2 domain; rows in 4-lane quads) ----
            float mx_r = -1e30f, mx_r8 = -1e30f;
            #pragma unroll
            for (int j = 0; j < 8; j++) {
                mx_r  = fmaxf(mx_r,  fmaxf(s[j][0], s[j][1]));
                mx_r8 = fmaxf(mx_r8, fmaxf(s[j][2], s[j][3]));
            }
            mx_r  = fmaxf(mx_r,  __shfl_xor_sync(0xffffffffu, mx_r,  1));
            mx_r  = fmaxf(mx_r,  __shfl_xor_sync(0xffffffffu, mx_r,  2));
            mx_r8 = fmaxf(mx_r8, __shfl_xor_sync(0xffffffffu, mx_r8, 1));
            mx_r8 = fmaxf(mx_r8, __shfl_xor_sync(0xffffffffu, mx_r8, 2));
            float mn_r  = fmaxf(m_r,  mx_r);
            float mn_r8 = fmaxf(m_r8, mx_r8);
            float corr_r  = ex2f(m_r  - mn_r);
            float corr_r8 = ex2f(m_r8 - mn_r8);
            m_r = mn_r; m_r8 = mn_r8;

            float ps_r = 0.0f, ps_r8 = 0.0f;
            unsigned ap[4][4];    // P as A-fragments; chunk c = keys 16c..16c+15
            #pragma unroll
            for (int j = 0; j < 8; j++) {
                float p0 = ex2f(s[j][0] - m_r);
                float p1 = ex2f(s[j][1] - m_r);
                float p2 = ex2f(s[j][2] - m_r8);
                float p3 = ex2f(s[j][3] - m_r8);
                ps_r  += p0 + p1;
                ps_r8 += p2 + p3;
                int c = j >> 1, hi = j & 1;
                ap[c][hi*2    ] = h2u(__floats2half2_rn(p0, p1));
                ap[c][hi*2 + 1] = h2u(__floats2half2_rn(p2, p3));
            }
            ps_r  += __shfl_xor_sync(0xffffffffu, ps_r,  1);
            ps_r  += __shfl_xor_sync(0xffffffffu, ps_r,  2);
            ps_r8 += __shfl_xor_sync(0xffffffffu, ps_r8, 1);
            ps_r8 += __shfl_xor_sync(0xffffffffu, ps_r8, 2);
            l_r  = l_r  * corr_r  + ps_r;
            l_r8 = l_r8 * corr_r8 + ps_r8;
            #pragma unroll
            for (int jd = 0; jd < 8; jd++) {
                oc[jd][0] *= corr_r;  oc[jd][1] *= corr_r;
                oc[jd][2] *= corr_r8; oc[jd][3] *= corr_r8;
            }

            // ---- O += P V ; V B-frags via ldmatrix.x4.trans ----
            const int lrow = lane & 15;
            const int lcol8 = (lane & 16) ? 8 : 0;
            #pragma unroll
            for (int c = 0; c < 4; c++) {
                #pragma unroll
                for (int jd2 = 0; jd2 < 4; jd2++) {
                    unsigned addr = (unsigned)__cvta_generic_to_shared(
                        (const char*)(Vbuf + (c*16 + lrow)*FS + jd2*8) + lcol8*2);
                    unsigned r0, r1, r2, r3;
                    ldsm4t(r0, r1, r2, r3, addr);
                    mmaf16(oc[2*jd2    ], ap[c][0], ap[c][1], ap[c][2], ap[c][3], r0, r1);
                    mmaf16(oc[2*jd2 + 1], ap[c][0], ap[c][1], ap[c][2], ap[c][3], r2, r3);
                }
            }
        }
        __syncthreads();
    }

    // ---- epilogue: normalize, store fp16 to [b*n][h*64+d] ----
    float inv_r = 1.0f / l_r, inv_r8 = 1.0f / l_r8;
    __half* o0 = g_attn + ((size_t)(b*N_ + row_r )*INNER + h*DH_);
    __half* o1 = g_attn + ((size_t)(b*N_ + row_r8)*INNER + h*DH_);
    #pragma unroll
    for (int jd = 0; jd < 8; jd++) {
        int c = jd*8 + 2*tig;
        *(__half2*)&o0[c] = __floats2half2_rn(oc[jd][0]*inv_r,  oc[jd][1]*inv_r );
        *(__half2*)&o1[c] = __floats2half2_rn(oc[jd][2]*inv_r8, oc[jd][3]*inv_r8);
    }
}

// =====================================================================
extern "C" void kernel_launch(void* const* d_in, const int* in_sizes, int n_in,
                              void* d_out, int out_size)
{
    const float* x   = (const float*)d_in[0];
    const float* Wq  = (const float*)d_in[1];
    const float* Wkv = (const float*)d_in[2];
    const float* Wo  = (const float*)d_in[3];
    const float* bo  = (const float*)d_in[4];
    float* out = (float*)d_out;

    __half* p_x;
    cudaGetSymbolAddress((void**)&p_x, g_x);

    cvt_h_kernel<<<(BN_*DIM_/4 + 255)/256, 256>>>((const float4*)x, (uint2*)p_x, BN_*DIM_/4);
    transp_all_kernel<<<dim3(64, 16), dim3(32, 8)>>>(Wq, Wkv, Wo);

    qkv_f16_kernel<<<dim3(12, 64), 256>>>();
    flash_f16_kernel<<<dim3(32, B_*H_), 256>>>();
    out_f16_kernel<<<dim3(4, 64), 256>>>(bo, out);
}

// round 9
// speedup vs baseline: 7.2077x; 1.0347x over previous
#include <cuda_runtime.h>
#include <cuda_fp16.h>

// Problem constants
#define B_    2
#define N_    4096
#define DIM_  512
#define H_    8
#define DH_   64
#define BN_   (B_*N_)          // 8192 rows
#define INNER (H_*DH_)         // 512

// ---------------- scratch (device globals; no runtime alloc) ----------------
__device__ __half g_x  [BN_*DIM_];         // x as fp16, [row][k]
__device__ __half g_WT [(3*INNER)*DIM_];   // [c][k]: 0..511 Wq cols, 512..1023 K, 1024..1535 V
__device__ __half g_WoT[DIM_*INNER];       // [n][k]
__device__ __half g_Q  [B_*H_*N_*DH_];     // [b][h][n][d], pre-scaled (1/64)*log2e
__device__ __half g_K  [B_*H_*N_*DH_];
__device__ __half g_V  [B_*H_*N_*DH_];
__device__ __half g_attn[BN_*INNER];       // [b*n][h*DH+d]

// ---------------- helpers ----------------
__device__ __forceinline__ void mmaf16(float* c, unsigned a0, unsigned a1,
                                       unsigned a2, unsigned a3,
                                       unsigned b0, unsigned b1) {
    asm("mma.sync.aligned.m16n8k16.row.col.f32.f16.f16.f32 "
        "{%0,%1,%2,%3}, {%4,%5,%6,%7}, {%8,%9}, {%0,%1,%2,%3};"
        : "+f"(c[0]), "+f"(c[1]), "+f"(c[2]), "+f"(c[3])
        : "r"(a0), "r"(a1), "r"(a2), "r"(a3), "r"(b0), "r"(b1));
}
// fp16 accumulator variant
__device__ __forceinline__ void mmaf16h(unsigned* c, unsigned a0, unsigned a1,
                                        unsigned a2, unsigned a3,
                                        unsigned b0, unsigned b1) {
    asm("mma.sync.aligned.m16n8k16.row.col.f16.f16.f16.f16 "
        "{%0,%1}, {%2,%3,%4,%5}, {%6,%7}, {%0,%1};"
        : "+r"(c[0]), "+r"(c[1])
        : "r"(a0), "r"(a1), "r"(a2), "r"(a3), "r"(b0), "r"(b1));
}
__device__ __forceinline__ void cpa16(void* smem_dst, const void* gsrc) {
    unsigned s = (unsigned)__cvta_generic_to_shared(smem_dst);
    asm volatile("cp.async.cg.shared.global [%0], [%1], 16;" :: "r"(s), "l"(gsrc));
}
__device__ __forceinline__ void cpa_commit() { asm volatile("cp.async.commit_group;"); }
template<int NN> __device__ __forceinline__ void cpa_wait() {
    asm volatile("cp.async.wait_group %0;" :: "n"(NN));
}
// non-trans ldmatrix x4 (for K: B = K^T, key=gid, dims in half2)
__device__ __forceinline__ void ldsm4(unsigned& r0, unsigned& r1,
                                      unsigned& r2, unsigned& r3, unsigned addr) {
    asm volatile("ldmatrix.sync.aligned.m8n8.x4.shared.b16 {%0,%1,%2,%3}, [%4];"
        : "=r"(r0), "=r"(r1), "=r"(r2), "=r"(r3) : "r"(addr));
}
__device__ __forceinline__ void ldsm4t(unsigned& r0, unsigned& r1,
                                       unsigned& r2, unsigned& r3, unsigned addr) {
    asm volatile("ldmatrix.sync.aligned.m8n8.x4.trans.shared.b16 {%0,%1,%2,%3}, [%4];"
        : "=r"(r0), "=r"(r1), "=r"(r2), "=r"(r3) : "r"(addr));
}
__device__ __forceinline__ void ldsm2t(unsigned& r0, unsigned& r1, unsigned addr) {
    asm volatile("ldmatrix.sync.aligned.m8n8.x2.trans.shared.b16 {%0,%1}, [%2];"
        : "=r"(r0), "=r"(r1) : "r"(addr));
}
__device__ __forceinline__ unsigned h2u(__half2 h) { return *(unsigned*)&h; }
__device__ __forceinline__ __half2 u2h(unsigned u) { return *(__half2*)&u; }
__device__ __forceinline__ float ex2f(float x) {
    float r; asm("ex2.approx.f32 %0, %1;" : "=f"(r) : "f"(x)); return r;
}
__device__ __forceinline__ unsigned ex2h2(unsigned x) {
    unsigned r; asm("ex2.approx.f16x2 %0, %1;" : "=r"(r) : "r"(x)); return r;
}

// =====================================================================
// Pre-pass kernels
// =====================================================================
__global__ void cvt_h_kernel(const float4* __restrict__ src,
                             uint2* __restrict__ dst, int n4)
{
    int i = blockIdx.x * blockDim.x + threadIdx.x;
    if (i < n4) {
        float4 v = src[i];
        uint2 o;
        o.x = h2u(__floats2half2_rn(v.x, v.y));
        o.y = h2u(__floats2half2_rn(v.z, v.w));
        dst[i] = o;
    }
}

__global__ void transp_all_kernel(const float* __restrict__ Wq,
                                  const float* __restrict__ Wkv,
                                  const float* __restrict__ Wo)
{
    __shared__ float s[32][33];
    const int bx = blockIdx.x;
    const float* src; int ldsrc, cg; __half* dst;
    if (bx < 16)      { src = Wq;  ldsrc = 512;  cg = bx;      dst = g_WT; }
    else if (bx < 48) { src = Wkv; ldsrc = 1024; cg = bx - 16; dst = g_WT + (size_t)512*DIM_; }
    else              { src = Wo;  ldsrc = 512;  cg = bx - 48; dst = g_WoT; }

    int c0 = cg * 32, k0 = blockIdx.y * 32;
    int tx = threadIdx.x, ty = threadIdx.y;   // (32, 8)
    #pragma unroll
    for (int i = 0; i < 32; i += 8)
        s[ty + i][tx] = src[(size_t)(k0 + ty + i) * ldsrc + c0 + tx];
    __syncthreads();
    #pragma unroll
    for (int i = 0; i < 32; i += 8)
        dst[(size_t)(c0 + ty + i) * 512 + k0 + tx] = __float2half_rn(s[tx][ty + i]);
}

// =====================================================================
// fp16 GEMM core (unchanged)
// =====================================================================
#define GS 20
#define GTILE (128*GS)

__device__ __forceinline__ void gemm_stage(const __half* __restrict__ A,
                                           const __half* __restrict__ W,
                                           int row0, int bcol0, int k0,
                                           unsigned* As, unsigned* Bs, int tid)
{
    #pragma unroll
    for (int i = 0; i < 2; i++) {
        int idx = tid + i*256;
        int r = idx >> 2, seg = idx & 3;
        cpa16(&As[r*GS + seg*4], &A[(size_t)(row0  + r)*512 + k0 + seg*8]);
        cpa16(&Bs[r*GS + seg*4], &W[(size_t)(bcol0 + r)*512 + k0 + seg*8]);
    }
}

__device__ __forceinline__ void gemm_f16(const __half* __restrict__ A,
                                         const __half* __restrict__ W,
                                         int row0, int bcol0,
                                         float (&acc)[4][4][4],
                                         unsigned* AsBuf, unsigned* BsBuf)
{
    const int tid  = threadIdx.x;
    const int lane = tid & 31, w = tid >> 5;
    const int gid  = lane >> 2, tig = lane & 3;
    const int m0w  = (w >> 2) * 64;
    const int n0w  = (w & 3) * 32;

    #pragma unroll
    for (int mt = 0; mt < 4; mt++)
        #pragma unroll
        for (int nt = 0; nt < 4; nt++)
            #pragma unroll
            for (int r = 0; r < 4; r++) acc[mt][nt][r] = 0.0f;

    gemm_stage(A, W, row0, bcol0, 0, AsBuf, BsBuf, tid);
    cpa_commit();

    for (int it = 0; it < 16; it++) {
        const int buf = it & 1;
        if (it + 1 < 16) {
            gemm_stage(A, W, row0, bcol0, (it+1)*32,
                       AsBuf + (buf^1)*GTILE, BsBuf + (buf^1)*GTILE, tid);
            cpa_commit();
            cpa_wait<1>();
        } else {
            cpa_wait<0>();
        }
        __syncthreads();

        const unsigned* As = AsBuf + buf*GTILE;
        const unsigned* Bs = BsBuf + buf*GTILE;
        #pragma unroll
        for (int kc = 0; kc < 2; kc++) {
            const int kk = kc * 8;
            unsigned am[4][4];
            #pragma unroll
            for (int mt = 0; mt < 4; mt++) {
                int mr = m0w + mt*16;
                am[mt][0] = As[(mr+gid  )*GS + kk + tig    ];
                am[mt][1] = As[(mr+gid+8)*GS + kk + tig    ];
                am[mt][2] = As[(mr+gid  )*GS + kk + tig + 4];
                am[mt][3] = As[(mr+gid+8)*GS + kk + tig + 4];
            }
            unsigned bn[4][2];
            #pragma unroll
            for (int nt = 0; nt < 4; nt++) {
                bn[nt][0] = Bs[(n0w+nt*8+gid)*GS + kk + tig    ];
                bn[nt][1] = Bs[(n0w+nt*8+gid)*GS + kk + tig + 4];
            }
            #pragma unroll
            for (int mt = 0; mt < 4; mt++)
                #pragma unroll
                for (int nt = 0; nt < 4; nt++)
                    mmaf16(acc[mt][nt], am[mt][0], am[mt][1], am[mt][2], am[mt][3],
                           bn[nt][0], bn[nt][1]);
        }
        __syncthreads();
    }
}

// ---- Kernel 1: QKV projection ----
#define QSCALE (1.44269504088896f / 64.0f)

__global__ __launch_bounds__(256, 2) void qkv_f16_kernel()
{
    __shared__ unsigned As[2*GTILE];
    __shared__ unsigned Bs[2*GTILE];

    const int bx = blockIdx.x;
    const int row0 = blockIdx.y * 128;
    const int which = bx >> 2;
    const int bcol0 = bx * 128;
    const int lcolbase = (bx & 3) * 128;

    float acc[4][4][4];
    gemm_f16(g_x, g_WT, row0, bcol0, acc, As, Bs);

    const float scale = (which == 0) ? QSCALE : 1.0f;
    __half* dst = (which == 0) ? g_Q : (which == 1 ? g_K : g_V);

    const int lane = threadIdx.x & 31, w = threadIdx.x >> 5;
    const int gid = lane >> 2, tig = lane & 3;
    const int m0w = (w >> 2) * 64, n0w = (w & 3) * 32;

    #pragma unroll
    for (int mt = 0; mt < 4; mt++) {
        int r0 = row0 + m0w + mt*16 + gid;
        int r1 = r0 + 8;
        int b0i = r0 >> 12, n0i = r0 & (N_-1);
        int b1i = r1 >> 12, n1i = r1 & (N_-1);
        #pragma unroll
        for (int nt = 0; nt < 4; nt++) {
            int c = lcolbase + n0w + nt*8 + 2*tig;
            int h = c >> 6, d = c & 63;
            __half2 v0 = __floats2half2_rn(acc[mt][nt][0]*scale, acc[mt][nt][1]*scale);
            __half2 v1 = __floats2half2_rn(acc[mt][nt][2]*scale, acc[mt][nt][3]*scale);
            *(__half2*)&dst[(((size_t)(b0i*H_ + h)*N_ + n0i)*DH_ + d)] = v0;
            *(__half2*)&dst[(((size_t)(b1i*H_ + h)*N_ + n1i)*DH_ + d)] = v1;
        }
    }
}

// ---- Kernel 3: out = g_attn @ WoT^T + bo ----
__global__ __launch_bounds__(256, 2) void out_f16_kernel(
    const float* __restrict__ bo, float* __restrict__ out)
{
    __shared__ unsigned As[2*GTILE];
    __shared__ unsigned Bs[2*GTILE];

    const int row0 = blockIdx.y * 128;
    const int wcol = blockIdx.x * 128;

    float acc[4][4][4];
    gemm_f16(g_attn, g_WoT, row0, wcol, acc, As, Bs);

    const int lane = threadIdx.x & 31, w = threadIdx.x >> 5;
    const int gid = lane >> 2, tig = lane & 3;
    const int m0w = (w >> 2) * 64, n0w = (w & 3) * 32;

    #pragma unroll
    for (int mt = 0; mt < 4; mt++) {
        int r0 = row0 + m0w + mt*16 + gid;
        int r1 = r0 + 8;
        #pragma unroll
        for (int nt = 0; nt < 4; nt++) {
            int c = wcol + n0w + nt*8 + 2*tig;
            float2 bias = *(const float2*)&bo[c];
            float2 v0 = make_float2(acc[mt][nt][0] + bias.x, acc[mt][nt][1] + bias.y);
            float2 v1 = make_float2(acc[mt][nt][2] + bias.x, acc[mt][nt][3] + bias.y);
            *(float2*)&out[(size_t)r0*512 + c] = v0;
            *(float2*)&out[(size_t)r1*512 + c] = v1;
        }
    }
}

// =====================================================================
// Kernel 2: causal flash attention — packed fp16 softmax pipeline.
//   K B-frags via NON-trans ldmatrix (B=K^T: key=gid, dims packed).
// =====================================================================
#define FS 36               // half2 stride per row (32 used + 4 pad)
#define KVT (64*FS)

__global__ __launch_bounds__(256, 2) void flash_f16_kernel()
{
    __shared__ unsigned SMEM[4*KVT];    // [K0 K1 V0 V1]; Q staged at front
    unsigned* Ks = SMEM;
    unsigned* Vs = SMEM + 2*KVT;

    const int bh = blockIdx.y, b = bh >> 3, h = bh & 7;
    const int tile = 31 - (int)blockIdx.x;
    const int tid = threadIdx.x, lane = tid & 31, w = tid >> 5;
    const int gid = lane >> 2, tig = lane & 3;

    const __half* Qb = g_Q + (size_t)bh * N_ * DH_;
    const __half* Kb = g_K + (size_t)bh * N_ * DH_;
    const __half* Vb = g_V + (size_t)bh * N_ * DH_;
    const int qrow0 = tile * 128;

    // ---- stage Q tile into front of SMEM ----
    #pragma unroll
    for (int i = 0; i < 4; i++) {
        int idx = tid + i*256;
        int rr = idx >> 3, seg = idx & 7;
        cpa16(&SMEM[rr*FS + seg*4], &Qb[(size_t)(qrow0+rr)*DH_ + seg*8]);
    }
    cpa_commit(); cpa_wait<0>();
    __syncthreads();
    unsigned aq[4][4];
    {
        const unsigned* Qw = SMEM + (16*w)*FS;
        #pragma unroll
        for (int c = 0; c < 4; c++) {
            aq[c][0] = Qw[(gid  )*FS + c*8 + tig    ];
            aq[c][1] = Qw[(gid+8)*FS + c*8 + tig    ];
            aq[c][2] = Qw[(gid  )*FS + c*8 + tig + 4];
            aq[c][3] = Qw[(gid+8)*FS + c*8 + tig + 4];
        }
    }
    __syncthreads();   // Q reads done before K/V staging reuses region

    // ---- init V ones-column padding (cols 64..71; staging only writes 0..63) ----
    if (tid < 128) {
        int rr = tid & 63, bu = tid >> 6;
        unsigned* vp = Vs + bu*KVT + rr*FS + 32;
        vp[0] = 0x00003C00u;   // (1.0h, 0.0h)
        vp[1] = 0u; vp[2] = 0u; vp[3] = 0u;
    }

    float oc[8][4];
    #pragma unroll
    for (int jd = 0; jd < 8; jd++)
        #pragma unroll
        for (int r = 0; r < 4; r++) oc[jd][r] = 0.0f;
    float cl0 = 0.0f, cl1 = 0.0f, cl2 = 0.0f, cl3 = 0.0f;
    float m_r = -1e30f, m_r8 = -1e30f;
    const int wrow_min = qrow0 + 16*w;
    const int row_r = wrow_min + gid, row_r8 = row_r + 8;

    const int nkt = (qrow0 + 128) / 64;

    // stage first K/V tile
    #pragma unroll
    for (int i = 0; i < 2; i++) {
        int idx = tid + i*256;
        int rr = idx >> 3, seg = idx & 7;
        cpa16(&Ks[rr*FS + seg*4], &Kb[(size_t)rr*DH_ + seg*8]);
        cpa16(&Vs[rr*FS + seg*4], &Vb[(size_t)rr*DH_ + seg*8]);
    }
    cpa_commit();

    for (int kt = 0; kt < nkt; kt++) {
        const int k0 = kt * 64;
        const int buf = kt & 1;
        if (kt + 1 < nkt) {
            const int kn = k0 + 64;
            unsigned* Kd = Ks + (buf^1)*KVT;
            unsigned* Vd = Vs + (buf^1)*KVT;
            #pragma unroll
            for (int i = 0; i < 2; i++) {
                int idx = tid + i*256;
                int rr = idx >> 3, seg = idx & 7;
                cpa16(&Kd[rr*FS + seg*4], &Kb[(size_t)(kn+rr)*DH_ + seg*8]);
                cpa16(&Vd[rr*FS + seg*4], &Vb[(size_t)(kn+rr)*DH_ + seg*8]);
            }
            cpa_commit();
            cpa_wait<1>();
        } else {
            cpa_wait<0>();
        }
        __syncthreads();

        const bool active = (k0 <= wrow_min + 15);
        if (active) {
            const unsigned* Kbuf = Ks + buf*KVT;
            const unsigned* Vbuf = Vs + buf*KVT;

            // ---- S = Q K^T, fp16 accumulators; K frags via NON-trans ldsm ----
            unsigned sh[8], sh8[8];
            #pragma unroll
            for (int j = 0; j < 8; j++) {
                unsigned sc2[2] = {0u, 0u};
                unsigned kA[4], kB[4];
                unsigned base = (unsigned)__cvta_generic_to_shared(
                    Kbuf + (j*8 + (lane & 7))*FS + ((lane >> 3) & 3)*4);
                ldsm4(kA[0], kA[1], kA[2], kA[3], base);          // dims 0..31
                ldsm4(kB[0], kB[1], kB[2], kB[3], base + 16*4);   // dims 32..63
                mmaf16h(sc2, aq[0][0], aq[0][1], aq[0][2], aq[0][3], kA[0], kA[1]);
                mmaf16h(sc2, aq[1][0], aq[1][1], aq[1][2], aq[1][3], kA[2], kA[3]);
                mmaf16h(sc2, aq[2][0], aq[2][1], aq[2][2], aq[2][3], kB[0], kB[1]);
                mmaf16h(sc2, aq[3][0], aq[3][1], aq[3][2], aq[3][3], kB[2], kB[3]);
                sh[j] = sc2[0]; sh8[j] = sc2[1];
            }
            // ---- causal mask: add {0,-inf} halves ----
            if (k0 + 63 > wrow_min) {
                #pragma unroll
                for (int j = 0; j < 8; j++) {
                    int c0 = k0 + j*8 + 2*tig;
                    unsigned mk  = (c0 > row_r  ? 0xFC00u : 0u) | (c0+1 > row_r  ? 0xFC000000u : 0u);
                    unsigned mk8 = (c0 > row_r8 ? 0xFC00u : 0u) | (c0+1 > row_r8 ? 0xFC000000u : 0u);
                    sh[j]  = h2u(__hadd2(u2h(sh[j]),  u2h(mk)));
                    sh8[j] = h2u(__hadd2(u2h(sh8[j]), u2h(mk8)));
                }
            }
            // ---- packed max ----
            __half2 mx2 = u2h(sh[0]), mx28 = u2h(sh8[0]);
            #pragma unroll
            for (int j = 1; j < 8; j++) {
                mx2  = __hmax2(mx2,  u2h(sh[j]));
                mx28 = __hmax2(mx28, u2h(sh8[j]));
            }
            float mx_r  = fmaxf(__low2float(mx2),  __high2float(mx2));
            float mx_r8 = fmaxf(__low2float(mx28), __high2float(mx28));
            mx_r  = fmaxf(mx_r,  __shfl_xor_sync(0xffffffffu, mx_r,  1));
            mx_r  = fmaxf(mx_r,  __shfl_xor_sync(0xffffffffu, mx_r,  2));
            mx_r8 = fmaxf(mx_r8, __shfl_xor_sync(0xffffffffu, mx_r8, 1));
            mx_r8 = fmaxf(mx_r8, __shfl_xor_sync(0xffffffffu, mx_r8, 2));
            float mn_r  = fmaxf(m_r,  mx_r);
            float mn_r8 = fmaxf(m_r8, mx_r8);
            float corr_r  = ex2f(m_r  - mn_r);
            float corr_r8 = ex2f(m_r8 - mn_r8);
            m_r = mn_r; m_r8 = mn_r8;
            __half2 m2r  = __float2half2_rn(m_r);
            __half2 m2r8 = __float2half2_rn(m_r8);

            // ---- p = ex2(s - m) in f16x2 -> PV A-fragments directly ----
            unsigned ap[4][4];
            #pragma unroll
            for (int j = 0; j < 8; j++) {
                unsigned p  = ex2h2(h2u(__hsub2(u2h(sh[j]),  m2r )));
                unsigned p8 = ex2h2(h2u(__hsub2(u2h(sh8[j]), m2r8)));
                int c = j >> 1, hi = j & 1;
                ap[c][hi*2    ] = p;
                ap[c][hi*2 + 1] = p8;
            }

            // ---- rescale O and l accumulators ----
            #pragma unroll
            for (int jd = 0; jd < 8; jd++) {
                oc[jd][0] *= corr_r;  oc[jd][1] *= corr_r;
                oc[jd][2] *= corr_r8; oc[jd][3] *= corr_r8;
            }
            cl0 *= corr_r; cl2 *= corr_r8;

            // ---- O += P V ; l += P 1 ----
            const int lrow = lane & 15;
            const int lcol8 = (lane & 16) ? 8 : 0;
            #pragma unroll
            for (int c = 0; c < 4; c++) {
                #pragma unroll
                for (int jd2 = 0; jd2 < 4; jd2++) {
                    unsigned addr = (unsigned)__cvta_generic_to_shared(
                        (const char*)(Vbuf + (c*16 + lrow)*FS + jd2*8) + lcol8*2);
                    unsigned r0, r1, r2, r3;
                    ldsm4t(r0, r1, r2, r3, addr);
                    mmaf16(oc[2*jd2    ], ap[c][0], ap[c][1], ap[c][2], ap[c][3], r0, r1);
                    mmaf16(oc[2*jd2 + 1], ap[c][0], ap[c][1], ap[c][2], ap[c][3], r2, r3);
                }
                unsigned laddr = (unsigned)__cvta_generic_to_shared(
                    Vbuf + (c*16 + lrow)*FS + 32);
                unsigned l0, l1;
                ldsm2t(l0, l1, laddr);
                float clf[4] = {cl0, cl1, cl2, cl3};
                mmaf16(clf, ap[c][0], ap[c][1], ap[c][2], ap[c][3], l0, l1);
                cl0 = clf[0]; cl1 = clf[1]; cl2 = clf[2]; cl3 = clf[3];
            }
        }
        __syncthreads();
    }

    // ---- epilogue: l lives in col 64 (tig==0 lanes); broadcast in quad ----
    float l_r  = __shfl_sync(0xffffffffu, cl0, lane & ~3);
    float l_r8 = __shfl_sync(0xffffffffu, cl2, lane & ~3);
    float inv_r = 1.0f / l_r, inv_r8 = 1.0f / l_r8;
    __half* o0 = g_attn + ((size_t)(b*N_ + row_r )*INNER + h*DH_);
    __half* o1 = g_attn + ((size_t)(b*N_ + row_r8)*INNER + h*DH_);
    #pragma unroll
    for (int jd = 0; jd < 8; jd++) {
        int c = jd*8 + 2*tig;
        *(__half2*)&o0[c] = __floats2half2_rn(oc[jd][0]*inv_r,  oc[jd][1]*inv_r );
        *(__half2*)&o1[c] = __floats2half2_rn(oc[jd][2]*inv_r8, oc[jd][3]*inv_r8);
    }
}

// =====================================================================
extern "C" void kernel_launch(void* const* d_in, const int* in_sizes, int n_in,
                              void* d_out, int out_size)
{
    const float* x   = (const float*)d_in[0];
    const float* Wq  = (const float*)d_in[1];
    const float* Wkv = (const float*)d_in[2];
    const float* Wo  = (const float*)d_in[3];
    const float* bo  = (const float*)d_in[4];
    float* out = (float*)d_out;

    __half* p_x;
    cudaGetSymbolAddress((void**)&p_x, g_x);

    cvt_h_kernel<<<(BN_*DIM_/4 + 255)/256, 256>>>((const float4*)x, (uint2*)p_x, BN_*DIM_/4);
    transp_all_kernel<<<dim3(64, 16), dim3(32, 8)>>>(Wq, Wkv, Wo);

    qkv_f16_kernel<<<dim3(12, 64), 256>>>();
    flash_f16_kernel<<<dim3(32, B_*H_), 256>>>();
    out_f16_kernel<<<dim3(4, 64), 256>>>(bo, out);
}

// round 11
// speedup vs baseline: 8.6978x; 1.2067x over previous
#include <cuda_runtime.h>
#include <cuda_fp16.h>

// Problem constants
#define B_    2
#define N_    4096
#define DIM_  512
#define H_    8
#define DH_   64
#define BN_   (B_*N_)          // 8192 rows
#define INNER (H_*DH_)         // 512

// ---------------- scratch (device globals; no runtime alloc) ----------------
__device__ __half g_x  [BN_*DIM_];         // x as fp16, [row][k]
__device__ __half g_WT [(3*INNER)*DIM_];   // [c][k]: 0..511 Wq cols, 512..1023 K, 1024..1535 V
__device__ __half g_WoT[DIM_*INNER];       // [n][k]
__device__ __half g_Q  [B_*H_*N_*DH_];     // [b][h][n][d], pre-scaled (1/64)*log2e
__device__ __half g_K  [B_*H_*N_*DH_];
__device__ __half g_V  [B_*H_*N_*DH_];
__device__ __half g_attn[BN_*INNER];       // [b*n][h*DH+d]

// ---------------- helpers ----------------
__device__ __forceinline__ void mmaf16(float* c, unsigned a0, unsigned a1,
                                       unsigned a2, unsigned a3,
                                       unsigned b0, unsigned b1) {
    asm("mma.sync.aligned.m16n8k16.row.col.f32.f16.f16.f32 "
        "{%0,%1,%2,%3}, {%4,%5,%6,%7}, {%8,%9}, {%0,%1,%2,%3};"
        : "+f"(c[0]), "+f"(c[1]), "+f"(c[2]), "+f"(c[3])
        : "r"(a0), "r"(a1), "r"(a2), "r"(a3), "r"(b0), "r"(b1));
}
__device__ __forceinline__ void mmaf16h(unsigned* c, unsigned a0, unsigned a1,
                                        unsigned a2, unsigned a3,
                                        unsigned b0, unsigned b1) {
    asm("mma.sync.aligned.m16n8k16.row.col.f16.f16.f16.f16 "
        "{%0,%1}, {%2,%3,%4,%5}, {%6,%7}, {%0,%1};"
        : "+r"(c[0]), "+r"(c[1])
        : "r"(a0), "r"(a1), "r"(a2), "r"(a3), "r"(b0), "r"(b1));
}
__device__ __forceinline__ void cpa16(void* smem_dst, const void* gsrc) {
    unsigned s = (unsigned)__cvta_generic_to_shared(smem_dst);
    asm volatile("cp.async.cg.shared.global [%0], [%1], 16;" :: "r"(s), "l"(gsrc));
}
__device__ __forceinline__ void cpa_commit() { asm volatile("cp.async.commit_group;"); }
template<int NN> __device__ __forceinline__ void cpa_wait() {
    asm volatile("cp.async.wait_group %0;" :: "n"(NN));
}
__device__ __forceinline__ void ldsm4(unsigned& r0, unsigned& r1,
                                      unsigned& r2, unsigned& r3, unsigned addr) {
    asm volatile("ldmatrix.sync.aligned.m8n8.x4.shared.b16 {%0,%1,%2,%3}, [%4];"
        : "=r"(r0), "=r"(r1), "=r"(r2), "=r"(r3) : "r"(addr));
}
__device__ __forceinline__ void ldsm4t(unsigned& r0, unsigned& r1,
                                       unsigned& r2, unsigned& r3, unsigned addr) {
    asm volatile("ldmatrix.sync.aligned.m8n8.x4.trans.shared.b16 {%0,%1,%2,%3}, [%4];"
        : "=r"(r0), "=r"(r1), "=r"(r2), "=r"(r3) : "r"(addr));
}
__device__ __forceinline__ void ldsm2t(unsigned& r0, unsigned& r1, unsigned addr) {
    asm volatile("ldmatrix.sync.aligned.m8n8.x2.trans.shared.b16 {%0,%1}, [%2];"
        : "=r"(r0), "=r"(r1) : "r"(addr));
}
__device__ __forceinline__ unsigned h2u(__half2 h) { return *(unsigned*)&h; }
__device__ __forceinline__ __half2 u2h(unsigned u) { return *(__half2*)&u; }
__device__ __forceinline__ float ex2f(float x) {
    float r; asm("ex2.approx.f32 %0, %1;" : "=f"(r) : "f"(x)); return r;
}
__device__ __forceinline__ unsigned ex2h2(unsigned x) {
    unsigned r; asm("ex2.approx.f16x2 %0, %1;" : "=r"(r) : "r"(x)); return r;
}

// =====================================================================
// Fused pre-pass: blocks 0..4095 convert x; blocks 4096..5119 transpose W.
// =====================================================================
__global__ void prepass_kernel(const float* __restrict__ x,
                               const float* __restrict__ Wq,
                               const float* __restrict__ Wkv,
                               const float* __restrict__ Wo)
{
    const int bid = blockIdx.x, tid = threadIdx.x;
    if (bid < 4096) {
        int i = bid * 256 + tid;                 // n4 = 1048576 exactly
        float4 v = ((const float4*)x)[i];
        uint2 o;
        o.x = h2u(__floats2half2_rn(v.x, v.y));
        o.y = h2u(__floats2half2_rn(v.z, v.w));
        ((uint2*)g_x)[i] = o;
    } else {
        __shared__ float s[32][33];
        int tb = bid - 4096;                     // 0..1023
        int bx = tb & 63, by = tb >> 6;          // (64, 16)
        const float* src; int ldsrc, cg; __half* dst;
        if (bx < 16)      { src = Wq;  ldsrc = 512;  cg = bx;      dst = g_WT; }
        else if (bx < 48) { src = Wkv; ldsrc = 1024; cg = bx - 16; dst = g_WT + (size_t)512*DIM_; }
        else              { src = Wo;  ldsrc = 512;  cg = bx - 48; dst = g_WoT; }
        int c0 = cg * 32, k0 = by * 32;
        int tx = tid & 31, ty = tid >> 5;        // (32, 8)
        #pragma unroll
        for (int i = 0; i < 32; i += 8)
            s[ty + i][tx] = src[(size_t)(k0 + ty + i) * ldsrc + c0 + tx];
        __syncthreads();
        #pragma unroll
        for (int i = 0; i < 32; i += 8)
            dst[(size_t)(c0 + ty + i) * 512 + k0 + tx] = __float2half_rn(s[tx][ty + i]);
    }
}

// =====================================================================
// fp16 GEMM core — single-sync pipelined loop
// =====================================================================
#define GS 20
#define GTILE (128*GS)

__device__ __forceinline__ void gemm_stage(const __half* __restrict__ A,
                                           const __half* __restrict__ W,
                                           int row0, int bcol0, int k0,
                                           unsigned* As, unsigned* Bs, int tid)
{
    #pragma unroll
    for (int i = 0; i < 2; i++) {
        int idx = tid + i*256;
        int r = idx >> 2, seg = idx & 3;
        cpa16(&As[r*GS + seg*4], &A[(size_t)(row0  + r)*512 + k0 + seg*8]);
        cpa16(&Bs[r*GS + seg*4], &W[(size_t)(bcol0 + r)*512 + k0 + seg*8]);
    }
}

__device__ __forceinline__ void gemm_f16(const __half* __restrict__ A,
                                         const __half* __restrict__ W,
                                         int row0, int bcol0,
                                         float (&acc)[4][4][4],
                                         unsigned* AsBuf, unsigned* BsBuf)
{
    const int tid  = threadIdx.x;
    const int lane = tid & 31, w = tid >> 5;
    const int gid  = lane >> 2, tig = lane & 3;
    const int m0w  = (w >> 2) * 64;
    const int n0w  = (w & 3) * 32;

    #pragma unroll
    for (int mt = 0; mt < 4; mt++)
        #pragma unroll
        for (int nt = 0; nt < 4; nt++)
            #pragma unroll
            for (int r = 0; r < 4; r++) acc[mt][nt][r] = 0.0f;

    gemm_stage(A, W, row0, bcol0, 0, AsBuf, BsBuf, tid);
    cpa_commit();

    for (int it = 0; it < 16; it++) {
        const int buf = it & 1;
        cpa_wait<0>();
        __syncthreads();
        if (it + 1 < 16) {
            gemm_stage(A, W, row0, bcol0, (it+1)*32,
                       AsBuf + (buf^1)*GTILE, BsBuf + (buf^1)*GTILE, tid);
            cpa_commit();
        }

        const unsigned* As = AsBuf + buf*GTILE;
        const unsigned* Bs = BsBuf + buf*GTILE;
        #pragma unroll
        for (int kc = 0; kc < 2; kc++) {
            const int kk = kc * 8;
            unsigned am[4][4];
            #pragma unroll
            for (int mt = 0; mt < 4; mt++) {
                int mr = m0w + mt*16;
                am[mt][0] = As[(mr+gid  )*GS + kk + tig    ];
                am[mt][1] = As[(mr+gid+8)*GS + kk + tig    ];
                am[mt][2] = As[(mr+gid  )*GS + kk + tig + 4];
                am[mt][3] = As[(mr+gid+8)*GS + kk + tig + 4];
            }
            unsigned bn[4][2];
            #pragma unroll
            for (int nt = 0; nt < 4; nt++) {
                bn[nt][0] = Bs[(n0w+nt*8+gid)*GS + kk + tig    ];
                bn[nt][1] = Bs[(n0w+nt*8+gid)*GS + kk + tig + 4];
            }
            #pragma unroll
            for (int mt = 0; mt < 4; mt++)
                #pragma unroll
                for (int nt = 0; nt < 4; nt++)
                    mmaf16(acc[mt][nt], am[mt][0], am[mt][1], am[mt][2], am[mt][3],
                           bn[nt][0], bn[nt][1]);
        }
    }
}

// ---- Kernel 1: QKV projection ----
#define QSCALE (1.44269504088896f / 64.0f)

__global__ __launch_bounds__(256, 2) void qkv_f16_kernel()
{
    __shared__ unsigned As[2*GTILE];
    __shared__ unsigned Bs[2*GTILE];

    const int bx = blockIdx.x;
    const int row0 = blockIdx.y * 128;
    const int which = bx >> 2;
    const int bcol0 = bx * 128;
    const int lcolbase = (bx & 3) * 128;

    float acc[4][4][4];
    gemm_f16(g_x, g_WT, row0, bcol0, acc, As, Bs);

    const float scale = (which == 0) ? QSCALE : 1.0f;
    __half* dst = (which == 0) ? g_Q : (which == 1 ? g_K : g_V);

    const int lane = threadIdx.x & 31, w = threadIdx.x >> 5;
    const int gid = lane >> 2, tig = lane & 3;
    const int m0w = (w >> 2) * 64, n0w = (w & 3) * 32;

    #pragma unroll
    for (int mt = 0; mt < 4; mt++) {
        int r0 = row0 + m0w + mt*16 + gid;
        int r1 = r0 + 8;
        int b0i = r0 >> 12, n0i = r0 & (N_-1);
        int b1i = r1 >> 12, n1i = r1 & (N_-1);
        #pragma unroll
        for (int nt = 0; nt < 4; nt++) {
            int c = lcolbase + n0w + nt*8 + 2*tig;
            int h = c >> 6, d = c & 63;
            __half2 v0 = __floats2half2_rn(acc[mt][nt][0]*scale, acc[mt][nt][1]*scale);
            __half2 v1 = __floats2half2_rn(acc[mt][nt][2]*scale, acc[mt][nt][3]*scale);
            *(__half2*)&dst[(((size_t)(b0i*H_ + h)*N_ + n0i)*DH_ + d)] = v0;
            *(__half2*)&dst[(((size_t)(b1i*H_ + h)*N_ + n1i)*DH_ + d)] = v1;
        }
    }
}

// ---- Kernel 3: out = g_attn @ WoT^T + bo ----
__global__ __launch_bounds__(256, 2) void out_f16_kernel(
    const float* __restrict__ bo, float* __restrict__ out)
{
    __shared__ unsigned As[2*GTILE];
    __shared__ unsigned Bs[2*GTILE];

    const int row0 = blockIdx.y * 128;
    const int wcol = blockIdx.x * 128;

    float acc[4][4][4];
    gemm_f16(g_attn, g_WoT, row0, wcol, acc, As, Bs);

    const int lane = threadIdx.x & 31, w = threadIdx.x >> 5;
    const int gid = lane >> 2, tig = lane & 3;
    const int m0w = (w >> 2) * 64, n0w = (w & 3) * 32;

    #pragma unroll
    for (int mt = 0; mt < 4; mt++) {
        int r0 = row0 + m0w + mt*16 + gid;
        int r1 = r0 + 8;
        #pragma unroll
        for (int nt = 0; nt < 4; nt++) {
            int c = wcol + n0w + nt*8 + 2*tig;
            float2 bias = *(const float2*)&bo[c];
            float2 v0 = make_float2(acc[mt][nt][0] + bias.x, acc[mt][nt][1] + bias.y);
            float2 v1 = make_float2(acc[mt][nt][2] + bias.x, acc[mt][nt][3] + bias.y);
            *(float2*)&out[(size_t)r0*512 + c] = v0;
            *(float2*)&out[(size_t)r1*512 + c] = v1;
        }
    }
}

// =====================================================================
// Kernel 2: causal flash attention — paired tiles (p, 31-p), single-sync.
//   grid (16, 16): x = pair index, y = (b,h). 256 equal-work blocks.
// =====================================================================
#define FS 36               // half2 stride per row (32 used + 4 pad)
#define KVT (64*FS)

__global__ __launch_bounds__(256, 2) void flash_f16_kernel()
{
    __shared__ unsigned SMEM[4*KVT];    // [K0 K1 V0 V1]; Q staged over K region
    unsigned* Ks = SMEM;
    unsigned* Vs = SMEM + 2*KVT;

    const int bh = blockIdx.y, b = bh >> 3, h = bh & 7;
    const int tid = threadIdx.x, lane = tid & 31, w = tid >> 5;
    const int gid = lane >> 2, tig = lane & 3;

    const __half* Qb = g_Q + (size_t)bh * N_ * DH_;
    const __half* Kb = g_K + (size_t)bh * N_ * DH_;
    const __half* Vb = g_V + (size_t)bh * N_ * DH_;

    // ---- init V ones-column padding once (cols 64..71; staging writes 0..63) ----
    if (tid < 128) {
        int rr = tid & 63, bu = tid >> 6;
        unsigned* vp = Vs + bu*KVT + rr*FS + 32;
        vp[0] = 0x00003C00u;   // (1.0h, 0.0h)
        vp[1] = 0u; vp[2] = 0u; vp[3] = 0u;
    }

    for (int half = 0; half < 2; half++) {
        const int tile = half ? (31 - (int)blockIdx.x) : (int)blockIdx.x;
        const int qrow0 = tile * 128;

        __syncthreads();   // prior compute done before Q staging reuses K region
        #pragma unroll
        for (int i = 0; i < 4; i++) {
            int idx = tid + i*256;
            int rr = idx >> 3, seg = idx & 7;
            cpa16(&SMEM[rr*FS + seg*4], &Qb[(size_t)(qrow0+rr)*DH_ + seg*8]);
        }
        cpa_commit(); cpa_wait<0>();
        __syncthreads();
        unsigned aq[4][4];
        {
            const unsigned* Qw = SMEM + (16*w)*FS;
            #pragma unroll
            for (int c = 0; c < 4; c++) {
                aq[c][0] = Qw[(gid  )*FS + c*8 + tig    ];
                aq[c][1] = Qw[(gid+8)*FS + c*8 + tig    ];
                aq[c][2] = Qw[(gid  )*FS + c*8 + tig + 4];
                aq[c][3] = Qw[(gid+8)*FS + c*8 + tig + 4];
            }
        }
        __syncthreads();   // Q reads done before K staging overwrites

        float oc[8][4];
        #pragma unroll
        for (int jd = 0; jd < 8; jd++)
            #pragma unroll
            for (int r = 0; r < 4; r++) oc[jd][r] = 0.0f;
        float cl0 = 0.0f, cl1 = 0.0f, cl2 = 0.0f, cl3 = 0.0f;
        float m_r = -1e30f, m_r8 = -1e30f;
        const int wrow_min = qrow0 + 16*w;
        const int row_r = wrow_min + gid, row_r8 = row_r + 8;

        const int nkt = (qrow0 + 128) / 64;

        // stage first K/V tile
        #pragma unroll
        for (int i = 0; i < 2; i++) {
            int idx = tid + i*256;
            int rr = idx >> 3, seg = idx & 7;
            cpa16(&Ks[rr*FS + seg*4], &Kb[(size_t)rr*DH_ + seg*8]);
            cpa16(&Vs[rr*FS + seg*4], &Vb[(size_t)rr*DH_ + seg*8]);
        }
        cpa_commit();

        for (int kt = 0; kt < nkt; kt++) {
            const int k0 = kt * 64;
            const int buf = kt & 1;
            cpa_wait<0>();
            __syncthreads();
            if (kt + 1 < nkt) {
                const int kn = k0 + 64;
                unsigned* Kd = Ks + (buf^1)*KVT;
                unsigned* Vd = Vs + (buf^1)*KVT;
                #pragma unroll
                for (int i = 0; i < 2; i++) {
                    int idx = tid + i*256;
                    int rr = idx >> 3, seg = idx & 7;
                    cpa16(&Kd[rr*FS + seg*4], &Kb[(size_t)(kn+rr)*DH_ + seg*8]);
                    cpa16(&Vd[rr*FS + seg*4], &Vb[(size_t)(kn+rr)*DH_ + seg*8]);
                }
                cpa_commit();
            }

            const bool active = (k0 <= wrow_min + 15);
            if (active) {
                const unsigned* Kbuf = Ks + buf*KVT;
                const unsigned* Vbuf = Vs + buf*KVT;

                // ---- S = Q K^T, fp16 accumulators; K frags non-trans ldsm ----
                unsigned sh[8], sh8[8];
                #pragma unroll
                for (int j = 0; j < 8; j++) {
                    unsigned sc2[2] = {0u, 0u};
                    unsigned kA[4], kB[4];
                    unsigned base = (unsigned)__cvta_generic_to_shared(
                        Kbuf + (j*8 + (lane & 7))*FS + ((lane >> 3) & 3)*4);
                    ldsm4(kA[0], kA[1], kA[2], kA[3], base);
                    ldsm4(kB[0], kB[1], kB[2], kB[3], base + 16*4);
                    mmaf16h(sc2, aq[0][0], aq[0][1], aq[0][2], aq[0][3], kA[0], kA[1]);
                    mmaf16h(sc2, aq[1][0], aq[1][1], aq[1][2], aq[1][3], kA[2], kA[3]);
                    mmaf16h(sc2, aq[2][0], aq[2][1], aq[2][2], aq[2][3], kB[0], kB[1]);
                    mmaf16h(sc2, aq[3][0], aq[3][1], aq[3][2], aq[3][3], kB[2], kB[3]);
                    sh[j] = sc2[0]; sh8[j] = sc2[1];
                }
                // ---- causal mask ----
                if (k0 + 63 > wrow_min) {
                    #pragma unroll
                    for (int j = 0; j < 8; j++) {
                        int c0 = k0 + j*8 + 2*tig;
                        unsigned mk  = (c0 > row_r  ? 0xFC00u : 0u) | (c0+1 > row_r  ? 0xFC000000u : 0u);
                        unsigned mk8 = (c0 > row_r8 ? 0xFC00u : 0u) | (c0+1 > row_r8 ? 0xFC000000u : 0u);
                        sh[j]  = h2u(__hadd2(u2h(sh[j]),  u2h(mk)));
                        sh8[j] = h2u(__hadd2(u2h(sh8[j]), u2h(mk8)));
                    }
                }
                // ---- packed max ----
                __half2 mx2 = u2h(sh[0]), mx28 = u2h(sh8[0]);
                #pragma unroll
                for (int j = 1; j < 8; j++) {
                    mx2  = __hmax2(mx2,  u2h(sh[j]));
                    mx28 = __hmax2(mx28, u2h(sh8[j]));
                }
                float mx_r  = fmaxf(__low2float(mx2),  __high2float(mx2));
                float mx_r8 = fmaxf(__low2float(mx28), __high2float(mx28));
                mx_r  = fmaxf(mx_r,  __shfl_xor_sync(0xffffffffu, mx_r,  1));
                mx_r  = fmaxf(mx_r,  __shfl_xor_sync(0xffffffffu, mx_r,  2));
                mx_r8 = fmaxf(mx_r8, __shfl_xor_sync(0xffffffffu, mx_r8, 1));
                mx_r8 = fmaxf(mx_r8, __shfl_xor_sync(0xffffffffu, mx_r8, 2));
                float mn_r  = fmaxf(m_r,  mx_r);
                float mn_r8 = fmaxf(m_r8, mx_r8);
                float corr_r  = ex2f(m_r  - mn_r);
                float corr_r8 = ex2f(m_r8 - mn_r8);
                m_r = mn_r; m_r8 = mn_r8;
                __half2 m2r  = __float2half2_rn(m_r);
                __half2 m2r8 = __float2half2_rn(m_r8);

                // ---- p = ex2(s - m) packed -> PV A-fragments ----
                unsigned ap[4][4];
                #pragma unroll
                for (int j = 0; j < 8; j++) {
                    unsigned p  = ex2h2(h2u(__hsub2(u2h(sh[j]),  m2r )));
                    unsigned p8 = ex2h2(h2u(__hsub2(u2h(sh8[j]), m2r8)));
                    int c = j >> 1, hi = j & 1;
                    ap[c][hi*2    ] = p;
                    ap[c][hi*2 + 1] = p8;
                }

                // ---- rescale accumulators ----
                #pragma unroll
                for (int jd = 0; jd < 8; jd++) {
                    oc[jd][0] *= corr_r;  oc[jd][1] *= corr_r;
                    oc[jd][2] *= corr_r8; oc[jd][3] *= corr_r8;
                }
                cl0 *= corr_r; cl2 *= corr_r8;

                // ---- O += P V ; l += P 1 ----
                const int lrow = lane & 15;
                const int lcol8 = (lane & 16) ? 8 : 0;
                #pragma unroll
                for (int c = 0; c < 4; c++) {
                    #pragma unroll
                    for (int jd2 = 0; jd2 < 4; jd2++) {
                        unsigned addr = (unsigned)__cvta_generic_to_shared(
                            (const char*)(Vbuf + (c*16 + lrow)*FS + jd2*8) + lcol8*2);
                        unsigned r0, r1, r2, r3;
                        ldsm4t(r0, r1, r2, r3, addr);
                        mmaf16(oc[2*jd2    ], ap[c][0], ap[c][1], ap[c][2], ap[c][3], r0, r1);
                        mmaf16(oc[2*jd2 + 1], ap[c][0], ap[c][1], ap[c][2], ap[c][3], r2, r3);
                    }
                    unsigned laddr = (unsigned)__cvta_generic_to_shared(
                        Vbuf + (c*16 + lrow)*FS + 32);
                    unsigned l0, l1;
                    ldsm2t(l0, l1, laddr);
                    float clf[4] = {cl0, cl1, cl2, cl3};
                    mmaf16(clf, ap[c][0], ap[c][1], ap[c][2], ap[c][3], l0, l1);
                    cl0 = clf[0]; cl1 = clf[1]; cl2 = clf[2]; cl3 = clf[3];
                }
            }
        }

        // ---- epilogue: l in col 64 (tig==0 lanes); broadcast in quad ----
        float l_r  = __shfl_sync(0xffffffffu, cl0, lane & ~3);
        float l_r8 = __shfl_sync(0xffffffffu, cl2, lane & ~3);
        float inv_r = 1.0f / l_r, inv_r8 = 1.0f / l_r8;
        __half* o0 = g_attn + ((size_t)(b*N_ + row_r )*INNER + h*DH_);
        __half* o1 = g_attn + ((size_t)(b*N_ + row_r8)*INNER + h*DH_);
        #pragma unroll
        for (int jd = 0; jd < 8; jd++) {
            int c = jd*8 + 2*tig;
            *(__half2*)&o0[c] = __floats2half2_rn(oc[jd][0]*inv_r,  oc[jd][1]*inv_r );
            *(__half2*)&o1[c] = __floats2half2_rn(oc[jd][2]*inv_r8, oc[jd][3]*inv_r8);
        }
    }
}

// =====================================================================
extern "C" void kernel_launch(void* const* d_in, const int* in_sizes, int n_in,
                              void* d_out, int out_size)
{
    const float* x   = (const float*)d_in[0];
    const float* Wq  = (const float*)d_in[1];
    const float* Wkv = (const float*)d_in[2];
    const float* Wo  = (const float*)d_in[3];
    const float* bo  = (const float*)d_in[4];
    float* out = (float*)d_out;

    prepass_kernel<<<4096 + 1024, 256>>>(x, Wq, Wkv, Wo);
    qkv_f16_kernel<<<dim3(12, 64), 256>>>();
    flash_f16_kernel<<<dim3(16, B_*H_), 256>>>();
    out_f16_kernel<<<dim3(4, 64), 256>>>(bo, out);
}